// round 1
// baseline (speedup 1.0000x reference)
#include <cuda_runtime.h>
#include <cstdint>

// Problem constants
#define LQ      43054
#define DMODEL  256
#define NHEADS  8
#define DHEAD   32
#define NLEV    4
#define NPTS    4

// Level geometry: (H,W) = (180,180),(90,90),(45,45),(23,23)
__device__ __constant__ int c_H[4]     = {180, 90, 45, 23};
__device__ __constant__ int c_W[4]     = {180, 90, 45, 23};
__device__ __constant__ int c_start[4] = {0, 32400, 40500, 42525};

// Scratch (device globals; no runtime allocation allowed)
__device__ float g_value[LQ * DMODEL];   // projected value  [Lq,256]
__device__ float g_smp[LQ * DMODEL];     // sampling offsets [Lq,256]
__device__ float g_logits[LQ * 128];     // attn logits      [Lq,128]
__device__ float g_acc[LQ * DMODEL];     // attention output [Lq,256] (head-major: h*32+d)

// ---------------------------------------------------------------------------
// SGEMM with bias: C[M,N] = A[M,K] @ B[K,N] + bias[N]
// BM=128, BN=128, BK=16, 256 threads, 8x8 microtile.
// Requires N % 128 == 0, K % 16 == 0. M guarded.
// ---------------------------------------------------------------------------
#define BM 128
#define BN 128
#define BK 16
#define TM 8
#define TN 8

__global__ __launch_bounds__(256) void sgemm_bias(
    int M, int N, int K,
    const float* __restrict__ A,
    const float* __restrict__ B,
    const float* __restrict__ bias,
    float* __restrict__ C)
{
    __shared__ float As[BK][BM];   // transposed A tile
    __shared__ float Bs[BK][BN];

    const int bm = blockIdx.y * BM;
    const int bn = blockIdx.x * BN;
    const int tid = threadIdx.x;

    const int trow = (tid / 16) * TM;   // 0..120
    const int tcol = (tid % 16) * TN;   // 0..120

    float acc[TM][TN];
#pragma unroll
    for (int i = 0; i < TM; i++)
#pragma unroll
        for (int j = 0; j < TN; j++) acc[i][j] = 0.f;

    for (int k0 = 0; k0 < K; k0 += BK) {
        // Load A tile: 128x16 = 512 float4, 2 per thread. Store transposed.
#pragma unroll
        for (int i = 0; i < 2; i++) {
            int f = tid + i * 256;
            int r = f >> 2;            // row in tile (0..127)
            int c4 = (f & 3) << 2;     // col in tile (0,4,8,12)
            int grow = bm + r;
            float4 v = make_float4(0.f, 0.f, 0.f, 0.f);
            if (grow < M)
                v = *(const float4*)&A[(size_t)grow * K + k0 + c4];
            As[c4 + 0][r] = v.x;
            As[c4 + 1][r] = v.y;
            As[c4 + 2][r] = v.z;
            As[c4 + 3][r] = v.w;
        }
        // Load B tile: 16x128 = 512 float4, 2 per thread.
#pragma unroll
        for (int i = 0; i < 2; i++) {
            int f = tid + i * 256;
            int r = f >> 5;            // row 0..15
            int c4 = (f & 31) << 2;    // col 0..124
            float4 v = *(const float4*)&B[(size_t)(k0 + r) * N + bn + c4];
            *(float4*)&Bs[r][c4] = v;
        }
        __syncthreads();

#pragma unroll
        for (int k = 0; k < BK; k++) {
            float ra[TM], rb[TN];
            float4 a0 = *(const float4*)&As[k][trow];
            float4 a1 = *(const float4*)&As[k][trow + 4];
            ra[0]=a0.x; ra[1]=a0.y; ra[2]=a0.z; ra[3]=a0.w;
            ra[4]=a1.x; ra[5]=a1.y; ra[6]=a1.z; ra[7]=a1.w;
            float4 b0 = *(const float4*)&Bs[k][tcol];
            float4 b1 = *(const float4*)&Bs[k][tcol + 4];
            rb[0]=b0.x; rb[1]=b0.y; rb[2]=b0.z; rb[3]=b0.w;
            rb[4]=b1.x; rb[5]=b1.y; rb[6]=b1.z; rb[7]=b1.w;
#pragma unroll
            for (int i = 0; i < TM; i++)
#pragma unroll
                for (int j = 0; j < TN; j++)
                    acc[i][j] = fmaf(ra[i], rb[j], acc[i][j]);
        }
        __syncthreads();
    }

    // Store with bias
#pragma unroll
    for (int i = 0; i < TM; i++) {
        int grow = bm + trow + i;
        if (grow < M) {
#pragma unroll
            for (int j = 0; j < TN; j += 4) {
                float4 v;
                v.x = acc[i][j + 0] + bias[bn + tcol + j + 0];
                v.y = acc[i][j + 1] + bias[bn + tcol + j + 1];
                v.z = acc[i][j + 2] + bias[bn + tcol + j + 2];
                v.w = acc[i][j + 3] + bias[bn + tcol + j + 3];
                *(float4*)&C[(size_t)grow * N + bn + tcol + j] = v;
            }
        }
    }
}

// ---------------------------------------------------------------------------
// Sampling kernel: one block per query, one warp per head, lane = channel.
// Lanes 0..15 own one (level,point) pair each: compute softmax weight,
// bilinear corner indices + combined weights; broadcast via shfl; all 32
// lanes gather 128B-coalesced value rows and FMA-accumulate.
// ---------------------------------------------------------------------------
__global__ __launch_bounds__(256) void msda_sample(
    const float* __restrict__ value,   // [Lq,256] projected
    const float* __restrict__ smp,     // [Lq,256] offsets
    const float* __restrict__ logits,  // [Lq,128]
    const float* __restrict__ rp,      // [Lq,4,2] reference points
    float* __restrict__ accb)          // [Lq,256] out (h*32+d)
{
    const int q = blockIdx.x;
    const int h = threadIdx.x >> 5;
    const int lane = threadIdx.x & 31;

    // ---- softmax over 16 logits of this head (full-warp reduce; hi lanes inert)
    float lg = -1e30f;
    if (lane < 16) lg = logits[q * 128 + h * 16 + lane];
    float m = lg;
#pragma unroll
    for (int s = 16; s > 0; s >>= 1)
        m = fmaxf(m, __shfl_xor_sync(0xffffffffu, m, s));
    float e = (lane < 16) ? __expf(lg - m) : 0.f;
    float ssum = e;
#pragma unroll
    for (int s = 16; s > 0; s >>= 1)
        ssum += __shfl_xor_sync(0xffffffffu, ssum, s);
    const float aw = e / ssum;

    // ---- per-lane (level,point) geometry
    int   idx[4] = {0, 0, 0, 0};
    float wt[4]  = {0.f, 0.f, 0.f, 0.f};
    if (lane < 16) {
        const int l = lane >> 2;
        const int p = lane & 3;
        const int Hl = c_H[l], Wl = c_W[l], st = c_start[l];
        const float rx = rp[(q * 4 + l) * 2 + 0];
        const float ry = rp[(q * 4 + l) * 2 + 1];
        const int oj = q * 256 + (((h * 4 + l) * 4) + p) * 2;
        const float ox = smp[oj + 0];
        const float oy = smp[oj + 1];
        // loc = ref + off/(W,H); x = loc_x*W - 0.5  =>  x = rx*W + ox - 0.5
        const float x = fmaf(rx, (float)Wl, ox) - 0.5f;
        const float y = fmaf(ry, (float)Hl, oy) - 0.5f;
        const float xf = floorf(x), yf = floorf(y);
        const float dx = x - xf, dy = y - yf;
        const int x0 = (int)xf, y0 = (int)yf;

#pragma unroll
        for (int c = 0; c < 4; c++) {
            const int xi = x0 + (c & 1);
            const int yi = y0 + (c >> 1);
            const bool v = (xi >= 0) && (xi < Wl) && (yi >= 0) && (yi < Hl);
            const int cx = min(max(xi, 0), Wl - 1);
            const int cy = min(max(yi, 0), Hl - 1);
            idx[c] = st + cy * Wl + cx;
            const float wx = (c & 1) ? dx : (1.f - dx);
            const float wy = (c >> 1) ? dy : (1.f - dy);
            wt[c] = v ? aw * wx * wy : 0.f;
        }
    }

    // ---- gather + accumulate (broadcast each point's corners to all lanes)
    const float* __restrict__ vb = value + (size_t)h * 32 + lane;
    float acc = 0.f;
#pragma unroll
    for (int i = 0; i < 16; i++) {
#pragma unroll
        for (int c = 0; c < 4; c++) {
            const int   id = __shfl_sync(0xffffffffu, idx[c], i);
            const float w  = __shfl_sync(0xffffffffu, wt[c], i);
            acc = fmaf(w, __ldg(vb + (size_t)id * 256), acc);
        }
    }
    accb[q * 256 + h * 32 + lane] = acc;
}

// ---------------------------------------------------------------------------
// Launch
// ---------------------------------------------------------------------------
extern "C" void kernel_launch(void* const* d_in, const int* in_sizes, int n_in,
                              void* d_out, int out_size)
{
    const float* query    = (const float*)d_in[0];
    const float* value_in = (const float*)d_in[1];
    const float* rp       = (const float*)d_in[2];
    const float* Wv       = (const float*)d_in[3];
    const float* bv       = (const float*)d_in[4];
    const float* Ws       = (const float*)d_in[5];
    const float* bs       = (const float*)d_in[6];
    const float* Wa       = (const float*)d_in[7];
    const float* ba       = (const float*)d_in[8];
    const float* Wo       = (const float*)d_in[9];
    const float* bo       = (const float*)d_in[10];
    float* out = (float*)d_out;

    float *pv, *ps, *pl, *pa;
    cudaGetSymbolAddress((void**)&pv, g_value);
    cudaGetSymbolAddress((void**)&ps, g_smp);
    cudaGetSymbolAddress((void**)&pl, g_logits);
    cudaGetSymbolAddress((void**)&pa, g_acc);

    const int M = LQ;
    dim3 blk(256);
    dim3 g256(256 / BN, (M + BM - 1) / BM);   // (2, 337)
    dim3 g128(128 / BN, (M + BM - 1) / BM);   // (1, 337)

    // Projections
    sgemm_bias<<<g256, blk>>>(M, 256, 256, value_in, Wv, bv, pv);
    sgemm_bias<<<g256, blk>>>(M, 256, 256, query,    Ws, bs, ps);
    sgemm_bias<<<g128, blk>>>(M, 128, 256, query,    Wa, ba, pl);

    // Deformable sampling
    msda_sample<<<M, 256>>>(pv, ps, pl, rp, pa);

    // Output projection
    sgemm_bias<<<g256, blk>>>(M, 256, 256, pa, Wo, bo, out);
}

// round 3
// speedup vs baseline: 1.3601x; 1.3601x over previous
#include <cuda_runtime.h>
#include <cuda_bf16.h>
#include <cstdint>

// Problem constants
#define LQ      43054
#define NHEADS  8
#define NLEV    4
#define NPTS    4

__device__ __constant__ int c_H[4]     = {180, 90, 45, 23};
__device__ __constant__ int c_W[4]     = {180, 90, 45, 23};
__device__ __constant__ int c_start[4] = {0, 32400, 40500, 42525};

// Scratch (device globals; no runtime allocation allowed)
__device__ float g_value[LQ * 256];
__device__ float g_smp[LQ * 256];
__device__ float g_logits[LQ * 128];
__device__ float g_acc[LQ * 256];
// pre-transposed + split weights: [N, 256] K-major, bf16 hi/lo
__device__ __nv_bfloat16 g_Wvh[256 * 256], g_Wvl[256 * 256];
__device__ __nv_bfloat16 g_Wsh[256 * 256], g_Wsl[256 * 256];
__device__ __nv_bfloat16 g_Wah[128 * 256], g_Wal[128 * 256];
__device__ __nv_bfloat16 g_Woh[256 * 256], g_Wol[256 * 256];

#define SW128(o) ((o) ^ (((o) >> 3) & 0x70))

__device__ __forceinline__ uint32_t smem_u32(const void* p) {
    uint32_t a;
    asm("{ .reg .u64 t; cvta.to.shared.u64 t, %1; cvt.u32.u64 %0, t; }" : "=r"(a) : "l"(p));
    return a;
}
__device__ __forceinline__ void ldsm4(uint32_t r[4], uint32_t addr) {
    asm volatile("ldmatrix.sync.aligned.m8n8.x4.shared.b16 {%0,%1,%2,%3}, [%4];"
        : "=r"(r[0]), "=r"(r[1]), "=r"(r[2]), "=r"(r[3]) : "r"(addr));
}
__device__ __forceinline__ void mma_bf16(float d[4], const uint32_t a[4],
                                         uint32_t b0, uint32_t b1) {
    asm volatile("mma.sync.aligned.m16n8k16.row.col.f32.bf16.bf16.f32 "
        "{%0,%1,%2,%3}, {%4,%5,%6,%7}, {%8,%9}, {%0,%1,%2,%3};"
        : "+f"(d[0]), "+f"(d[1]), "+f"(d[2]), "+f"(d[3])
        : "r"(a[0]), "r"(a[1]), "r"(a[2]), "r"(a[3]), "r"(b0), "r"(b1));
}
__device__ __forceinline__ uint32_t packbf2(float x, float y) {
    __nv_bfloat162 h = __floats2bfloat162_rn(x, y);
    return *(uint32_t*)&h;
}

// ---------------------------------------------------------------------------
// Tensor-core GEMM via mma.sync bf16 split-3:
//   C[M,N] = A[M,256] @ W[256,N] + bias
// A fp32 row-major; Bh/Bl pre-transposed [N,256] K-major bf16 (hi/lo split).
// CTA: 128(M) x 128(N), 256 threads, 8 warps as 4(m) x 2(n), warp tile 32x64.
// K chunks of 64, SW128-swizzled smem tiles (pitch 128B).
// ---------------------------------------------------------------------------
__global__ __launch_bounds__(256) void gemm_mma(
    const float* __restrict__ A,
    const __nv_bfloat16* __restrict__ Bh,
    const __nv_bfloat16* __restrict__ Bl,
    const float* __restrict__ bias,
    float* __restrict__ C, int M, int N)
{
    extern __shared__ char smem[];
    const uint32_t sb = smem_u32(smem);
    constexpr int OFF_AH = 0, OFF_AL = 16384, OFF_BH = 32768, OFF_BL = 49152;

    const int tid = threadIdx.x;
    const int wid = tid >> 5, lane = tid & 31;
    const int wm = (wid & 3) * 32;       // warp m offset in CTA tile
    const int wn = (wid >> 2) * 64;      // warp n offset
    const int bm = blockIdx.y * 128;
    const int bn = blockIdx.x * 128;

    float acc[2][8][4];
#pragma unroll
    for (int i = 0; i < 2; i++)
#pragma unroll
        for (int j = 0; j < 8; j++)
#pragma unroll
            for (int k = 0; k < 4; k++) acc[i][j][k] = 0.f;

    // per-lane ldmatrix row patterns
    const int a_row = lane & 15;                       // + wm + mt*16
    const int a_k8  = (lane >> 4) << 3;                // 0 or 8 (elements)
    const int b_row = (lane & 7) + ((lane & 16) >> 1); // n within 16-group
    const int b_k8  = lane & 8;                        // 0 or 8 (elements)

    // loader indices: 2 threads per row, each handles 32 k-elements
    const int ld_row = tid >> 1;
    const int ld_kh  = (tid & 1) * 32;

    for (int c = 0; c < 4; c++) {
        const int k0 = c * 64;

        // ---- A chunk [128m x 64k]: fp32 -> split bf16 hi/lo, swizzled
        {
            const int grow = bm + ld_row;
            const bool ok = grow < M;
            const float4* src = (const float4*)&A[(size_t)(ok ? grow : 0) * 256 + k0 + ld_kh];
#pragma unroll
            for (int jj = 0; jj < 4; jj++) {
                float4 v0 = ok ? src[jj * 2 + 0] : make_float4(0.f, 0.f, 0.f, 0.f);
                float4 v1 = ok ? src[jj * 2 + 1] : make_float4(0.f, 0.f, 0.f, 0.f);
                float vs[8] = {v0.x, v0.y, v0.z, v0.w, v1.x, v1.y, v1.z, v1.w};
                uint4 hi4, lo4;
                uint32_t* hp = (uint32_t*)&hi4;
                uint32_t* lp = (uint32_t*)&lo4;
#pragma unroll
                for (int i = 0; i < 4; i++) {
                    float a0 = vs[2 * i], a1 = vs[2 * i + 1];
                    __nv_bfloat16 h0 = __float2bfloat16(a0);
                    __nv_bfloat16 h1 = __float2bfloat16(a1);
                    hp[i] = packbf2(a0, a1);  // rn to bf16 pair
                    lp[i] = packbf2(a0 - __bfloat162float(h0),
                                    a1 - __bfloat162float(h1));
                }
                uint32_t off = SW128((uint32_t)(ld_row * 128 + (ld_kh + jj * 8) * 2));
                *(uint4*)(smem + OFF_AH + off) = hi4;
                *(uint4*)(smem + OFF_AL + off) = lo4;
            }
        }
        // ---- B chunk [128n x 64k]: bf16 hi/lo, swizzled
        {
            const int n = bn + ld_row;
            const uint4* sh = (const uint4*)&Bh[(size_t)n * 256 + k0 + ld_kh];
            const uint4* sl = (const uint4*)&Bl[(size_t)n * 256 + k0 + ld_kh];
#pragma unroll
            for (int jj = 0; jj < 4; jj++) {
                uint32_t off = SW128((uint32_t)(ld_row * 128 + (ld_kh + jj * 8) * 2));
                *(uint4*)(smem + OFF_BH + off) = sh[jj];
                *(uint4*)(smem + OFF_BL + off) = sl[jj];
            }
        }
        __syncthreads();

        // ---- MMA over 4 k16-steps
#pragma unroll
        for (int ks = 0; ks < 4; ks++) {
            uint32_t ah[2][4], al[2][4];
#pragma unroll
            for (int mt = 0; mt < 2; mt++) {
                uint32_t aoff = (uint32_t)((wm + mt * 16 + a_row) * 128 +
                                           (ks * 16 + a_k8) * 2);
                aoff = SW128(aoff);
                ldsm4(ah[mt], sb + OFF_AH + aoff);
                ldsm4(al[mt], sb + OFF_AL + aoff);
            }
#pragma unroll
            for (int ng = 0; ng < 4; ng++) {
                uint32_t boff = (uint32_t)((wn + ng * 16 + b_row) * 128 +
                                           (ks * 16 + b_k8) * 2);
                boff = SW128(boff);
                uint32_t bh4[4], bl4[4];
                ldsm4(bh4, sb + OFF_BH + boff);
                ldsm4(bl4, sb + OFF_BL + boff);
#pragma unroll
                for (int mt = 0; mt < 2; mt++) {
                    mma_bf16(acc[mt][ng * 2 + 0], ah[mt], bh4[0], bh4[1]);
                    mma_bf16(acc[mt][ng * 2 + 0], al[mt], bh4[0], bh4[1]);
                    mma_bf16(acc[mt][ng * 2 + 0], ah[mt], bl4[0], bl4[1]);
                    mma_bf16(acc[mt][ng * 2 + 1], ah[mt], bh4[2], bh4[3]);
                    mma_bf16(acc[mt][ng * 2 + 1], al[mt], bh4[2], bh4[3]);
                    mma_bf16(acc[mt][ng * 2 + 1], ah[mt], bl4[2], bl4[3]);
                }
            }
        }
        __syncthreads();
    }

    // ---- epilogue: d-frag rows g=(lane>>2), cols (lane&3)*2
    const int g = lane >> 2;
    const int cbase = bn + wn + (lane & 3) * 2;
#pragma unroll
    for (int nt = 0; nt < 8; nt++) {
        const int col = cbase + nt * 8;
        const float b0 = bias[col], b1 = bias[col + 1];
#pragma unroll
        for (int mt = 0; mt < 2; mt++) {
            int r0 = bm + wm + mt * 16 + g;
            if (r0 < M) {
                float2* d = (float2*)&C[(size_t)r0 * N + col];
                d[0] = make_float2(acc[mt][nt][0] + b0, acc[mt][nt][1] + b1);
            }
            int r1 = r0 + 8;
            if (r1 < M) {
                float2* d = (float2*)&C[(size_t)r1 * N + col];
                d[0] = make_float2(acc[mt][nt][2] + b0, acc[mt][nt][3] + b1);
            }
        }
    }
}

// ---------------------------------------------------------------------------
// Weight prep: transpose [256,N] -> [N,256] and split fp32 -> bf16 hi/lo
// ---------------------------------------------------------------------------
__global__ void transpose_split(const float* __restrict__ W, int N,
                                __nv_bfloat16* __restrict__ hi,
                                __nv_bfloat16* __restrict__ lo)
{
    int idx = blockIdx.x * 256 + threadIdx.x;
    if (idx >= 256 * N) return;
    int k = idx / N, n = idx % N;
    float v = W[idx];
    __nv_bfloat16 h = __float2bfloat16(v);
    hi[n * 256 + k] = h;
    lo[n * 256 + k] = __float2bfloat16(v - __bfloat162float(h));
}

// ---------------------------------------------------------------------------
// Sampling kernel: block=query, warp=head, lane=channel (as in R1)
// ---------------------------------------------------------------------------
__global__ __launch_bounds__(256) void msda_sample(
    const float* __restrict__ value,
    const float* __restrict__ smp,
    const float* __restrict__ logits,
    const float* __restrict__ rp,
    float* __restrict__ accb)
{
    const int q = blockIdx.x;
    const int h = threadIdx.x >> 5;
    const int lane = threadIdx.x & 31;

    float lg = -1e30f;
    if (lane < 16) lg = logits[q * 128 + h * 16 + lane];
    float m = lg;
#pragma unroll
    for (int s = 16; s > 0; s >>= 1)
        m = fmaxf(m, __shfl_xor_sync(0xffffffffu, m, s));
    float e = (lane < 16) ? __expf(lg - m) : 0.f;
    float ssum = e;
#pragma unroll
    for (int s = 16; s > 0; s >>= 1)
        ssum += __shfl_xor_sync(0xffffffffu, ssum, s);
    const float aw = e / ssum;

    int   idx[4] = {0, 0, 0, 0};
    float wt[4]  = {0.f, 0.f, 0.f, 0.f};
    if (lane < 16) {
        const int l = lane >> 2;
        const int p = lane & 3;
        const int Hl = c_H[l], Wl = c_W[l], st = c_start[l];
        const float rx = rp[(q * 4 + l) * 2 + 0];
        const float ry = rp[(q * 4 + l) * 2 + 1];
        const int oj = q * 256 + (((h * 4 + l) * 4) + p) * 2;
        const float ox = smp[oj + 0];
        const float oy = smp[oj + 1];
        const float x = fmaf(rx, (float)Wl, ox) - 0.5f;
        const float y = fmaf(ry, (float)Hl, oy) - 0.5f;
        const float xf = floorf(x), yf = floorf(y);
        const float dx = x - xf, dy = y - yf;
        const int x0 = (int)xf, y0 = (int)yf;

#pragma unroll
        for (int c = 0; c < 4; c++) {
            const int xi = x0 + (c & 1);
            const int yi = y0 + (c >> 1);
            const bool v = (xi >= 0) && (xi < Wl) && (yi >= 0) && (yi < Hl);
            const int cx = min(max(xi, 0), Wl - 1);
            const int cy = min(max(yi, 0), Hl - 1);
            idx[c] = st + cy * Wl + cx;
            const float wx = (c & 1) ? dx : (1.f - dx);
            const float wy = (c >> 1) ? dy : (1.f - dy);
            wt[c] = v ? aw * wx * wy : 0.f;
        }
    }

    const float* __restrict__ vb = value + (size_t)h * 32 + lane;
    float acc = 0.f;
#pragma unroll
    for (int i = 0; i < 16; i++) {
#pragma unroll
        for (int c = 0; c < 4; c++) {
            const int   id = __shfl_sync(0xffffffffu, idx[c], i);
            const float w  = __shfl_sync(0xffffffffu, wt[c], i);
            acc = fmaf(w, __ldg(vb + (size_t)id * 256), acc);
        }
    }
    accb[q * 256 + h * 32 + lane] = acc;
}

// ---------------------------------------------------------------------------
// Launch
// ---------------------------------------------------------------------------
extern "C" void kernel_launch(void* const* d_in, const int* in_sizes, int n_in,
                              void* d_out, int out_size)
{
    const float* query    = (const float*)d_in[0];
    const float* value_in = (const float*)d_in[1];
    const float* rp       = (const float*)d_in[2];
    const float* Wv       = (const float*)d_in[3];
    const float* bv       = (const float*)d_in[4];
    const float* Ws       = (const float*)d_in[5];
    const float* bs       = (const float*)d_in[6];
    const float* Wa       = (const float*)d_in[7];
    const float* ba       = (const float*)d_in[8];
    const float* Wo       = (const float*)d_in[9];
    const float* bo       = (const float*)d_in[10];
    float* out = (float*)d_out;

    float *pv, *ps, *pl, *pa;
    cudaGetSymbolAddress((void**)&pv, g_value);
    cudaGetSymbolAddress((void**)&ps, g_smp);
    cudaGetSymbolAddress((void**)&pl, g_logits);
    cudaGetSymbolAddress((void**)&pa, g_acc);
    __nv_bfloat16 *wvh, *wvl, *wsh, *wsl, *wah, *wal, *woh, *wol;
    cudaGetSymbolAddress((void**)&wvh, g_Wvh);
    cudaGetSymbolAddress((void**)&wvl, g_Wvl);
    cudaGetSymbolAddress((void**)&wsh, g_Wsh);
    cudaGetSymbolAddress((void**)&wsl, g_Wsl);
    cudaGetSymbolAddress((void**)&wah, g_Wah);
    cudaGetSymbolAddress((void**)&wal, g_Wal);
    cudaGetSymbolAddress((void**)&woh, g_Woh);
    cudaGetSymbolAddress((void**)&wol, g_Wol);

    const int SMEM = 65536;
    cudaFuncSetAttribute(gemm_mma, cudaFuncAttributeMaxDynamicSharedMemorySize, SMEM);

    const int M = LQ;
    const int GBY = (M + 127) / 128;  // 337
    dim3 blk(256);

    // Weight prep (tiny)
    transpose_split<<<(256 * 256 + 255) / 256, 256>>>(Wv, 256, wvh, wvl);
    transpose_split<<<(256 * 256 + 255) / 256, 256>>>(Ws, 256, wsh, wsl);
    transpose_split<<<(256 * 128 + 255) / 256, 256>>>(Wa, 128, wah, wal);
    transpose_split<<<(256 * 256 + 255) / 256, 256>>>(Wo, 256, woh, wol);

    // Projections on tensor cores (HMMA)
    gemm_mma<<<dim3(2, GBY), blk, SMEM>>>(value_in, wvh, wvl, bv, pv, M, 256);
    gemm_mma<<<dim3(2, GBY), blk, SMEM>>>(query,    wsh, wsl, bs, ps, M, 256);
    gemm_mma<<<dim3(1, GBY), blk, SMEM>>>(query,    wah, wal, ba, pl, M, 128);

    // Deformable sampling
    msda_sample<<<M, 256>>>(pv, ps, pl, rp, pa);

    // Output projection
    gemm_mma<<<dim3(2, GBY), blk, SMEM>>>(pa, woh, wol, bo, out, M, 256);
}

// round 4
// speedup vs baseline: 1.3928x; 1.0240x over previous
#include <cuda_runtime.h>
#include <cuda_bf16.h>
#include <cstdint>

// Problem constants
#define LQ      43054
#define NHEADS  8
#define NLEV    4
#define NPTS    4

// Scratch (device globals; no runtime allocation allowed)
__device__ float g_value[LQ * 256];
__device__ float g_smp[LQ * 256];
__device__ float g_logits[LQ * 128];
__device__ float g_acc[LQ * 256];
// pre-transposed + split weights: [N, 256] K-major, bf16 hi/lo
__device__ __nv_bfloat16 g_Wvh[256 * 256], g_Wvl[256 * 256];
__device__ __nv_bfloat16 g_Wsh[256 * 256], g_Wsl[256 * 256];
__device__ __nv_bfloat16 g_Wah[128 * 256], g_Wal[128 * 256];
__device__ __nv_bfloat16 g_Woh[256 * 256], g_Wol[256 * 256];

#define SW128(o) ((o) ^ (((o) >> 3) & 0x70))

__device__ __forceinline__ uint32_t smem_u32(const void* p) {
    uint32_t a;
    asm("{ .reg .u64 t; cvta.to.shared.u64 t, %1; cvt.u32.u64 %0, t; }" : "=r"(a) : "l"(p));
    return a;
}
__device__ __forceinline__ void ldsm4(uint32_t r[4], uint32_t addr) {
    asm volatile("ldmatrix.sync.aligned.m8n8.x4.shared.b16 {%0,%1,%2,%3}, [%4];"
        : "=r"(r[0]), "=r"(r[1]), "=r"(r[2]), "=r"(r[3]) : "r"(addr));
}
__device__ __forceinline__ void mma_bf16(float d[4], const uint32_t a[4],
                                         uint32_t b0, uint32_t b1) {
    asm volatile("mma.sync.aligned.m16n8k16.row.col.f32.bf16.bf16.f32 "
        "{%0,%1,%2,%3}, {%4,%5,%6,%7}, {%8,%9}, {%0,%1,%2,%3};"
        : "+f"(d[0]), "+f"(d[1]), "+f"(d[2]), "+f"(d[3])
        : "r"(a[0]), "r"(a[1]), "r"(a[2]), "r"(a[3]), "r"(b0), "r"(b1));
}
__device__ __forceinline__ uint32_t packbf2(float x, float y) {
    __nv_bfloat162 h = __floats2bfloat162_rn(x, y);
    return *(uint32_t*)&h;
}

// ---------------------------------------------------------------------------
// Tensor-core GEMM via mma.sync bf16 split-3 (unchanged from R3):
//   C[M,N] = A[M,256] @ W[256,N] + bias
// ---------------------------------------------------------------------------
__global__ __launch_bounds__(256) void gemm_mma(
    const float* __restrict__ A,
    const __nv_bfloat16* __restrict__ Bh,
    const __nv_bfloat16* __restrict__ Bl,
    const float* __restrict__ bias,
    float* __restrict__ C, int M, int N)
{
    extern __shared__ char smem[];
    const uint32_t sb = smem_u32(smem);
    constexpr int OFF_AH = 0, OFF_AL = 16384, OFF_BH = 32768, OFF_BL = 49152;

    const int tid = threadIdx.x;
    const int wid = tid >> 5, lane = tid & 31;
    const int wm = (wid & 3) * 32;
    const int wn = (wid >> 2) * 64;
    const int bm = blockIdx.y * 128;
    const int bn = blockIdx.x * 128;

    float acc[2][8][4];
#pragma unroll
    for (int i = 0; i < 2; i++)
#pragma unroll
        for (int j = 0; j < 8; j++)
#pragma unroll
            for (int k = 0; k < 4; k++) acc[i][j][k] = 0.f;

    const int a_row = lane & 15;
    const int a_k8  = (lane >> 4) << 3;
    const int b_row = (lane & 7) + ((lane & 16) >> 1);
    const int b_k8  = lane & 8;

    const int ld_row = tid >> 1;
    const int ld_kh  = (tid & 1) * 32;

    for (int c = 0; c < 4; c++) {
        const int k0 = c * 64;

        {
            const int grow = bm + ld_row;
            const bool ok = grow < M;
            const float4* src = (const float4*)&A[(size_t)(ok ? grow : 0) * 256 + k0 + ld_kh];
#pragma unroll
            for (int jj = 0; jj < 4; jj++) {
                float4 v0 = ok ? src[jj * 2 + 0] : make_float4(0.f, 0.f, 0.f, 0.f);
                float4 v1 = ok ? src[jj * 2 + 1] : make_float4(0.f, 0.f, 0.f, 0.f);
                float vs[8] = {v0.x, v0.y, v0.z, v0.w, v1.x, v1.y, v1.z, v1.w};
                uint4 hi4, lo4;
                uint32_t* hp = (uint32_t*)&hi4;
                uint32_t* lp = (uint32_t*)&lo4;
#pragma unroll
                for (int i = 0; i < 4; i++) {
                    float a0 = vs[2 * i], a1 = vs[2 * i + 1];
                    __nv_bfloat16 h0 = __float2bfloat16(a0);
                    __nv_bfloat16 h1 = __float2bfloat16(a1);
                    hp[i] = packbf2(a0, a1);
                    lp[i] = packbf2(a0 - __bfloat162float(h0),
                                    a1 - __bfloat162float(h1));
                }
                uint32_t off = SW128((uint32_t)(ld_row * 128 + (ld_kh + jj * 8) * 2));
                *(uint4*)(smem + OFF_AH + off) = hi4;
                *(uint4*)(smem + OFF_AL + off) = lo4;
            }
        }
        {
            const int n = bn + ld_row;
            const uint4* sh = (const uint4*)&Bh[(size_t)n * 256 + k0 + ld_kh];
            const uint4* sl = (const uint4*)&Bl[(size_t)n * 256 + k0 + ld_kh];
#pragma unroll
            for (int jj = 0; jj < 4; jj++) {
                uint32_t off = SW128((uint32_t)(ld_row * 128 + (ld_kh + jj * 8) * 2));
                *(uint4*)(smem + OFF_BH + off) = sh[jj];
                *(uint4*)(smem + OFF_BL + off) = sl[jj];
            }
        }
        __syncthreads();

#pragma unroll
        for (int ks = 0; ks < 4; ks++) {
            uint32_t ah[2][4], al[2][4];
#pragma unroll
            for (int mt = 0; mt < 2; mt++) {
                uint32_t aoff = (uint32_t)((wm + mt * 16 + a_row) * 128 +
                                           (ks * 16 + a_k8) * 2);
                aoff = SW128(aoff);
                ldsm4(ah[mt], sb + OFF_AH + aoff);
                ldsm4(al[mt], sb + OFF_AL + aoff);
            }
#pragma unroll
            for (int ng = 0; ng < 4; ng++) {
                uint32_t boff = (uint32_t)((wn + ng * 16 + b_row) * 128 +
                                           (ks * 16 + b_k8) * 2);
                boff = SW128(boff);
                uint32_t bh4[4], bl4[4];
                ldsm4(bh4, sb + OFF_BH + boff);
                ldsm4(bl4, sb + OFF_BL + boff);
#pragma unroll
                for (int mt = 0; mt < 2; mt++) {
                    mma_bf16(acc[mt][ng * 2 + 0], ah[mt], bh4[0], bh4[1]);
                    mma_bf16(acc[mt][ng * 2 + 0], al[mt], bh4[0], bh4[1]);
                    mma_bf16(acc[mt][ng * 2 + 0], ah[mt], bl4[0], bl4[1]);
                    mma_bf16(acc[mt][ng * 2 + 1], ah[mt], bh4[2], bh4[3]);
                    mma_bf16(acc[mt][ng * 2 + 1], al[mt], bh4[2], bh4[3]);
                    mma_bf16(acc[mt][ng * 2 + 1], ah[mt], bl4[2], bl4[3]);
                }
            }
        }
        __syncthreads();
    }

    const int g = lane >> 2;
    const int cbase = bn + wn + (lane & 3) * 2;
#pragma unroll
    for (int nt = 0; nt < 8; nt++) {
        const int col = cbase + nt * 8;
        const float b0 = bias[col], b1 = bias[col + 1];
#pragma unroll
        for (int mt = 0; mt < 2; mt++) {
            int r0 = bm + wm + mt * 16 + g;
            if (r0 < M) {
                float2* d = (float2*)&C[(size_t)r0 * N + col];
                d[0] = make_float2(acc[mt][nt][0] + b0, acc[mt][nt][1] + b1);
            }
            int r1 = r0 + 8;
            if (r1 < M) {
                float2* d = (float2*)&C[(size_t)r1 * N + col];
                d[0] = make_float2(acc[mt][nt][2] + b0, acc[mt][nt][3] + b1);
            }
        }
    }
}

// ---------------------------------------------------------------------------
// Weight prep: all 4 weights in one launch.
// Segments: Wv(N=256), Ws(N=256), Wa(N=128), Wo(N=256)
// ---------------------------------------------------------------------------
__global__ void prep_weights(const float* __restrict__ Wv,
                             const float* __restrict__ Ws,
                             const float* __restrict__ Wa,
                             const float* __restrict__ Wo,
                             __nv_bfloat16* __restrict__ vh, __nv_bfloat16* __restrict__ vl,
                             __nv_bfloat16* __restrict__ sh, __nv_bfloat16* __restrict__ sl,
                             __nv_bfloat16* __restrict__ ah, __nv_bfloat16* __restrict__ al,
                             __nv_bfloat16* __restrict__ oh, __nv_bfloat16* __restrict__ ol)
{
    int idx = blockIdx.x * 256 + threadIdx.x;
    const float* W;
    __nv_bfloat16 *hi, *lo;
    int N, base;
    if (idx < 65536)        { W = Wv; hi = vh; lo = vl; N = 256; base = 0; }
    else if (idx < 131072)  { W = Ws; hi = sh; lo = sl; N = 256; base = 65536; }
    else if (idx < 163840)  { W = Wa; hi = ah; lo = al; N = 128; base = 131072; }
    else if (idx < 229376)  { W = Wo; hi = oh; lo = ol; N = 256; base = 163840; }
    else return;
    int j = idx - base;
    int k = j / N, n = j % N;
    float v = W[j];
    __nv_bfloat16 h = __float2bfloat16(v);
    hi[n * 256 + k] = h;
    lo[n * 256 + k] = __float2bfloat16(v - __bfloat162float(h));
}

// ---------------------------------------------------------------------------
// Sampling kernel v2: block=query, warp=head.
// Lane split: c = lane>>3 (bilinear corner), e = lane&7 (channel group, 4ch).
// One LDG.128 per point fetches all 4 corners (4x fewer load instructions).
// Geometry lanes (0..15, one per (level,point)) broadcast x,y,aw per point;
// every lane computes its own corner index/weight. Corner reduction is a
// single 2-round shfl tree at the end.
// ---------------------------------------------------------------------------
__global__ __launch_bounds__(256) void msda_sample(
    const float* __restrict__ value,
    const float* __restrict__ smp,
    const float* __restrict__ logits,
    const float* __restrict__ rp,
    float* __restrict__ accb)
{
    constexpr int HH[4] = {180, 90, 45, 23};
    constexpr int WW[4] = {180, 90, 45, 23};
    constexpr int ST[4] = {0, 32400, 40500, 42525};

    const int q = blockIdx.x;
    const int h = threadIdx.x >> 5;
    const int lane = threadIdx.x & 31;
    const int cr = lane >> 3;      // corner 0..3
    const int e  = lane & 7;       // channel group

    // ---- softmax over this head's 16 logits (lanes 0..15 hold them)
    float lg = -1e30f;
    if (lane < 16) lg = logits[q * 128 + h * 16 + lane];
    float m = lg;
#pragma unroll
    for (int s = 16; s > 0; s >>= 1)
        m = fmaxf(m, __shfl_xor_sync(0xffffffffu, m, s));
    float eo = (lane < 16) ? __expf(lg - m) : 0.f;
    float ssum = eo;
#pragma unroll
    for (int s = 16; s > 0; s >>= 1)
        ssum += __shfl_xor_sync(0xffffffffu, ssum, s);
    const float aw = eo / ssum;

    // ---- geometry lanes: continuous sample position (x,y) per (level,point)
    float gx = 0.f, gy = 0.f;
    if (lane < 16) {
        const int l = lane >> 2;
        const int p = lane & 3;
        const int Hl = HH[l], Wl = WW[l];
        const float rx = rp[(q * 4 + l) * 2 + 0];
        const float ry = rp[(q * 4 + l) * 2 + 1];
        const int oj = q * 256 + (((h * 4 + l) * 4) + p) * 2;
        gx = fmaf(rx, (float)Wl, smp[oj + 0]) - 0.5f;
        gy = fmaf(ry, (float)Hl, smp[oj + 1]) - 0.5f;
    }

    const float* __restrict__ vbase = value + h * 32 + e * 4;
    float4 acc = make_float4(0.f, 0.f, 0.f, 0.f);
    const int cx1 = cr & 1, cy1 = cr >> 1;

#pragma unroll
    for (int i = 0; i < 16; i++) {
        const int l = i >> 2;                 // compile-time
        const int Hl = HH[l], Wl = WW[l], st = ST[l];
        const float x = __shfl_sync(0xffffffffu, gx, i);
        const float y = __shfl_sync(0xffffffffu, gy, i);
        const float w0 = __shfl_sync(0xffffffffu, aw, i);

        const float xf = floorf(x), yf = floorf(y);
        const float dx = x - xf, dy = y - yf;
        const int xi = (int)xf + cx1;
        const int yi = (int)yf + cy1;
        const bool v = (xi >= 0) & (xi < Wl) & (yi >= 0) & (yi < Hl);
        const int cx = min(max(xi, 0), Wl - 1);
        const int cy = min(max(yi, 0), Hl - 1);
        const int idx = st + cy * Wl + cx;
        const float wx = cx1 ? dx : (1.f - dx);
        const float wy = cy1 ? dy : (1.f - dy);
        const float w = v ? w0 * wx * wy : 0.f;

        const float4 vv = *(const float4*)(vbase + (size_t)idx * 256);
        acc.x = fmaf(w, vv.x, acc.x);
        acc.y = fmaf(w, vv.y, acc.y);
        acc.z = fmaf(w, vv.z, acc.z);
        acc.w = fmaf(w, vv.w, acc.w);
    }

    // ---- reduce over the 4 corner groups (xor lanes 8 and 16)
#pragma unroll
    for (int s = 8; s <= 16; s <<= 1) {
        acc.x += __shfl_xor_sync(0xffffffffu, acc.x, s);
        acc.y += __shfl_xor_sync(0xffffffffu, acc.y, s);
        acc.z += __shfl_xor_sync(0xffffffffu, acc.z, s);
        acc.w += __shfl_xor_sync(0xffffffffu, acc.w, s);
    }
    if (lane < 8)
        *(float4*)&accb[q * 256 + h * 32 + lane * 4] = acc;
}

// ---------------------------------------------------------------------------
// Launch
// ---------------------------------------------------------------------------
extern "C" void kernel_launch(void* const* d_in, const int* in_sizes, int n_in,
                              void* d_out, int out_size)
{
    const float* query    = (const float*)d_in[0];
    const float* value_in = (const float*)d_in[1];
    const float* rp       = (const float*)d_in[2];
    const float* Wv       = (const float*)d_in[3];
    const float* bv       = (const float*)d_in[4];
    const float* Ws       = (const float*)d_in[5];
    const float* bs       = (const float*)d_in[6];
    const float* Wa       = (const float*)d_in[7];
    const float* ba       = (const float*)d_in[8];
    const float* Wo       = (const float*)d_in[9];
    const float* bo       = (const float*)d_in[10];
    float* out = (float*)d_out;

    float *pv, *ps, *pl, *pa;
    cudaGetSymbolAddress((void**)&pv, g_value);
    cudaGetSymbolAddress((void**)&ps, g_smp);
    cudaGetSymbolAddress((void**)&pl, g_logits);
    cudaGetSymbolAddress((void**)&pa, g_acc);
    __nv_bfloat16 *wvh, *wvl, *wsh, *wsl, *wah, *wal, *woh, *wol;
    cudaGetSymbolAddress((void**)&wvh, g_Wvh);
    cudaGetSymbolAddress((void**)&wvl, g_Wvl);
    cudaGetSymbolAddress((void**)&wsh, g_Wsh);
    cudaGetSymbolAddress((void**)&wsl, g_Wsl);
    cudaGetSymbolAddress((void**)&wah, g_Wah);
    cudaGetSymbolAddress((void**)&wal, g_Wal);
    cudaGetSymbolAddress((void**)&woh, g_Woh);
    cudaGetSymbolAddress((void**)&wol, g_Wol);

    const int SMEM = 65536;
    cudaFuncSetAttribute(gemm_mma, cudaFuncAttributeMaxDynamicSharedMemorySize, SMEM);

    const int M = LQ;
    const int GBY = (M + 127) / 128;  // 337
    dim3 blk(256);

    // Weight prep (single launch)
    prep_weights<<<(229376 + 255) / 256, 256>>>(Wv, Ws, Wa, Wo,
                                                wvh, wvl, wsh, wsl,
                                                wah, wal, woh, wol);

    // Projections on tensor cores (HMMA)
    gemm_mma<<<dim3(2, GBY), blk, SMEM>>>(value_in, wvh, wvl, bv, pv, M, 256);
    gemm_mma<<<dim3(2, GBY), blk, SMEM>>>(query,    wsh, wsl, bs, ps, M, 256);
    gemm_mma<<<dim3(1, GBY), blk, SMEM>>>(query,    wah, wal, ba, pl, M, 128);

    // Deformable sampling
    msda_sample<<<M, 256>>>(pv, ps, pl, rp, pa);

    // Output projection
    gemm_mma<<<dim3(2, GBY), blk, SMEM>>>(pa, woh, wol, bo, out, M, 256);
}

// round 5
// speedup vs baseline: 1.5903x; 1.1418x over previous
#include <cuda_runtime.h>
#include <cuda_bf16.h>
#include <cuda_fp16.h>
#include <cstdint>

// Problem constants
#define LQ      43054
#define NHEADS  8

// Scratch (device globals; no runtime allocation allowed)
__device__ __half g_value_h[LQ * 256];          // projected value, fp16
__device__ float  g_qout[LQ * 384];             // [0,256)=offsets, [256,384)=logits
__device__ __nv_bfloat16 g_acch[LQ * 256];      // msda out hi
__device__ __nv_bfloat16 g_accl[LQ * 256];      // msda out lo
// pre-transposed + split weights: [N, 256] K-major, bf16 hi/lo
__device__ __nv_bfloat16 g_Wvh[256 * 256], g_Wvl[256 * 256];
__device__ __nv_bfloat16 g_Wqh[384 * 256], g_Wql[384 * 256];   // merged Ws|Wa
__device__ __nv_bfloat16 g_Woh[256 * 256], g_Wol[256 * 256];
__device__ float g_bq[384];                     // merged bias bs|ba

#define SW128(o) ((o) ^ (((o) >> 3) & 0x70))

__device__ __forceinline__ uint32_t smem_u32(const void* p) {
    uint32_t a;
    asm("{ .reg .u64 t; cvta.to.shared.u64 t, %1; cvt.u32.u64 %0, t; }" : "=r"(a) : "l"(p));
    return a;
}
__device__ __forceinline__ void ldsm4(uint32_t r[4], uint32_t addr) {
    asm volatile("ldmatrix.sync.aligned.m8n8.x4.shared.b16 {%0,%1,%2,%3}, [%4];"
        : "=r"(r[0]), "=r"(r[1]), "=r"(r[2]), "=r"(r[3]) : "r"(addr));
}
__device__ __forceinline__ void mma_bf16(float d[4], const uint32_t a[4],
                                         uint32_t b0, uint32_t b1) {
    asm volatile("mma.sync.aligned.m16n8k16.row.col.f32.bf16.bf16.f32 "
        "{%0,%1,%2,%3}, {%4,%5,%6,%7}, {%8,%9}, {%0,%1,%2,%3};"
        : "+f"(d[0]), "+f"(d[1]), "+f"(d[2]), "+f"(d[3])
        : "r"(a[0]), "r"(a[1]), "r"(a[2]), "r"(a[3]), "r"(b0), "r"(b1));
}
__device__ __forceinline__ uint32_t packbf2(float x, float y) {
    __nv_bfloat162 h = __floats2bfloat162_rn(x, y);
    return *(uint32_t*)&h;
}

// ---------------------------------------------------------------------------
// Tensor-core GEMM via mma.sync bf16 split-3 with register-staged pipeline.
//   C[M,N] = A[M,256] @ W[256,N] + bias
// ASPLIT=false: A fp32 row-major (split in-kernel).
// ASPLIT=true : A given pre-split bf16 hi/lo [M,256] row-major.
// OUTHALF: write C as fp16 (value path) instead of fp32.
// CTA 128x128, 256 thr, 8 warps (4m x 2n), K chunks of 64, SW128 smem.
// ---------------------------------------------------------------------------
template <bool ASPLIT, bool OUTHALF>
__global__ __launch_bounds__(256) void gemm_mma(
    const float* __restrict__ A,
    const __nv_bfloat16* __restrict__ AhG,
    const __nv_bfloat16* __restrict__ AlG,
    const __nv_bfloat16* __restrict__ Bh,
    const __nv_bfloat16* __restrict__ Bl,
    const float* __restrict__ bias,
    float* __restrict__ C,
    __half* __restrict__ Ch,
    int M, int N)
{
    extern __shared__ char smem[];
    const uint32_t sb = smem_u32(smem);
    constexpr int OFF_AH = 0, OFF_AL = 16384, OFF_BH = 32768, OFF_BL = 49152;

    const int tid = threadIdx.x;
    const int wid = tid >> 5, lane = tid & 31;
    const int wm = (wid & 3) * 32;
    const int wn = (wid >> 2) * 64;
    const int bm = blockIdx.y * 128;
    const int bn = blockIdx.x * 128;

    float acc[2][8][4];
#pragma unroll
    for (int i = 0; i < 2; i++)
#pragma unroll
        for (int j = 0; j < 8; j++)
#pragma unroll
            for (int k = 0; k < 4; k++) acc[i][j][k] = 0.f;

    const int a_row = lane & 15;
    const int a_k8  = (lane >> 4) << 3;
    const int b_row = (lane & 7) + ((lane & 16) >> 1);
    const int b_k8  = lane & 8;

    const int ld_row = tid >> 1;          // 0..127
    const int ld_kh  = (tid & 1) * 32;    // 0 or 32 (k elements)
    const int grow   = bm + ld_row;
    const bool okA   = grow < M;

    // register staging buffers
    float4 vA[8];                 // !ASPLIT: fp32 A chunk (32 elems)
    uint4  sAh[4], sAl[4];        // ASPLIT: bf16 A chunk hi/lo
    uint4  sBh[4], sBl[4];        // B chunk hi/lo

    // ---- stage chunk 0
    auto stage = [&](int c) {
        const int k0 = c * 64;
        if (!ASPLIT) {
            const float4* src = (const float4*)&A[(size_t)(okA ? grow : 0) * 256 + k0 + ld_kh];
#pragma unroll
            for (int j = 0; j < 8; j++)
                vA[j] = okA ? src[j] : make_float4(0.f, 0.f, 0.f, 0.f);
        } else {
            const uint4* sh = (const uint4*)&AhG[(size_t)(okA ? grow : 0) * 256 + k0 + ld_kh];
            const uint4* sl = (const uint4*)&AlG[(size_t)(okA ? grow : 0) * 256 + k0 + ld_kh];
#pragma unroll
            for (int j = 0; j < 4; j++) {
                sAh[j] = okA ? sh[j] : make_uint4(0, 0, 0, 0);
                sAl[j] = okA ? sl[j] : make_uint4(0, 0, 0, 0);
            }
        }
        const int n = bn + ld_row;
        const uint4* bh = (const uint4*)&Bh[(size_t)n * 256 + k0 + ld_kh];
        const uint4* bl = (const uint4*)&Bl[(size_t)n * 256 + k0 + ld_kh];
#pragma unroll
        for (int j = 0; j < 4; j++) {
            sBh[j] = bh[j];
            sBl[j] = bl[j];
        }
    };
    auto commit = [&]() {
        if (!ASPLIT) {
#pragma unroll
            for (int jj = 0; jj < 4; jj++) {
                float4 v0 = vA[jj * 2 + 0];
                float4 v1 = vA[jj * 2 + 1];
                float vs[8] = {v0.x, v0.y, v0.z, v0.w, v1.x, v1.y, v1.z, v1.w};
                uint4 hi4, lo4;
                uint32_t* hp = (uint32_t*)&hi4;
                uint32_t* lp = (uint32_t*)&lo4;
#pragma unroll
                for (int i = 0; i < 4; i++) {
                    float a0 = vs[2 * i], a1 = vs[2 * i + 1];
                    __nv_bfloat16 h0 = __float2bfloat16(a0);
                    __nv_bfloat16 h1 = __float2bfloat16(a1);
                    hp[i] = packbf2(a0, a1);
                    lp[i] = packbf2(a0 - __bfloat162float(h0),
                                    a1 - __bfloat162float(h1));
                }
                uint32_t off = SW128((uint32_t)(ld_row * 128 + (ld_kh + jj * 8) * 2));
                *(uint4*)(smem + OFF_AH + off) = hi4;
                *(uint4*)(smem + OFF_AL + off) = lo4;
            }
        } else {
#pragma unroll
            for (int jj = 0; jj < 4; jj++) {
                uint32_t off = SW128((uint32_t)(ld_row * 128 + (ld_kh + jj * 8) * 2));
                *(uint4*)(smem + OFF_AH + off) = sAh[jj];
                *(uint4*)(smem + OFF_AL + off) = sAl[jj];
            }
        }
#pragma unroll
        for (int jj = 0; jj < 4; jj++) {
            uint32_t off = SW128((uint32_t)(ld_row * 128 + (ld_kh + jj * 8) * 2));
            *(uint4*)(smem + OFF_BH + off) = sBh[jj];
            *(uint4*)(smem + OFF_BL + off) = sBl[jj];
        }
    };

    stage(0);
    for (int c = 0; c < 4; c++) {
        if (c > 0) __syncthreads();       // previous mma done before overwrite
        commit();
        __syncthreads();
        if (c < 3) stage(c + 1);          // issue next chunk's loads early

#pragma unroll
        for (int ks = 0; ks < 4; ks++) {
            uint32_t ah[2][4], al[2][4];
#pragma unroll
            for (int mt = 0; mt < 2; mt++) {
                uint32_t aoff = (uint32_t)((wm + mt * 16 + a_row) * 128 +
                                           (ks * 16 + a_k8) * 2);
                aoff = SW128(aoff);
                ldsm4(ah[mt], sb + OFF_AH + aoff);
                ldsm4(al[mt], sb + OFF_AL + aoff);
            }
#pragma unroll
            for (int ng = 0; ng < 4; ng++) {
                uint32_t boff = (uint32_t)((wn + ng * 16 + b_row) * 128 +
                                           (ks * 16 + b_k8) * 2);
                boff = SW128(boff);
                uint32_t bh4[4], bl4[4];
                ldsm4(bh4, sb + OFF_BH + boff);
                ldsm4(bl4, sb + OFF_BL + boff);
#pragma unroll
                for (int mt = 0; mt < 2; mt++) {
                    mma_bf16(acc[mt][ng * 2 + 0], ah[mt], bh4[0], bh4[1]);
                    mma_bf16(acc[mt][ng * 2 + 0], al[mt], bh4[0], bh4[1]);
                    mma_bf16(acc[mt][ng * 2 + 0], ah[mt], bl4[0], bl4[1]);
                    mma_bf16(acc[mt][ng * 2 + 1], ah[mt], bh4[2], bh4[3]);
                    mma_bf16(acc[mt][ng * 2 + 1], al[mt], bh4[2], bh4[3]);
                    mma_bf16(acc[mt][ng * 2 + 1], ah[mt], bl4[2], bl4[3]);
                }
            }
        }
    }

    // ---- epilogue
    const int g = lane >> 2;
    const int cbase = bn + wn + (lane & 3) * 2;
#pragma unroll
    for (int nt = 0; nt < 8; nt++) {
        const int col = cbase + nt * 8;
        const float b0 = bias[col], b1 = bias[col + 1];
#pragma unroll
        for (int mt = 0; mt < 2; mt++) {
            int r0 = bm + wm + mt * 16 + g;
            if (r0 < M) {
                if (OUTHALF) {
                    __half2 hv = __floats2half2_rn(acc[mt][nt][0] + b0, acc[mt][nt][1] + b1);
                    *(__half2*)&Ch[(size_t)r0 * N + col] = hv;
                } else {
                    *(float2*)&C[(size_t)r0 * N + col] =
                        make_float2(acc[mt][nt][0] + b0, acc[mt][nt][1] + b1);
                }
            }
            int r1 = r0 + 8;
            if (r1 < M) {
                if (OUTHALF) {
                    __half2 hv = __floats2half2_rn(acc[mt][nt][2] + b0, acc[mt][nt][3] + b1);
                    *(__half2*)&Ch[(size_t)r1 * N + col] = hv;
                } else {
                    *(float2*)&C[(size_t)r1 * N + col] =
                        make_float2(acc[mt][nt][2] + b0, acc[mt][nt][3] + b1);
                }
            }
        }
    }
}

// ---------------------------------------------------------------------------
// Weight prep: Wv -> g_Wv*, Ws|Wa -> merged g_Wq* (N=384), Wo -> g_Wo*,
// plus merged bias bs|ba -> g_bq. One launch.
// ---------------------------------------------------------------------------
__global__ void prep_weights(const float* __restrict__ Wv,
                             const float* __restrict__ Ws,
                             const float* __restrict__ Wa,
                             const float* __restrict__ Wo,
                             const float* __restrict__ bs,
                             const float* __restrict__ ba,
                             __nv_bfloat16* __restrict__ vh, __nv_bfloat16* __restrict__ vl,
                             __nv_bfloat16* __restrict__ qh, __nv_bfloat16* __restrict__ ql,
                             __nv_bfloat16* __restrict__ oh, __nv_bfloat16* __restrict__ ol,
                             float* __restrict__ bq)
{
    int idx = blockIdx.x * 256 + threadIdx.x;
    const float* W;
    __nv_bfloat16 *hi, *lo;
    int N, base, nofs;
    if (idx < 65536)        { W = Wv; hi = vh; lo = vl; N = 256; base = 0;      nofs = 0; }
    else if (idx < 131072)  { W = Ws; hi = qh; lo = ql; N = 256; base = 65536;  nofs = 0; }
    else if (idx < 163840)  { W = Wa; hi = qh; lo = ql; N = 128; base = 131072; nofs = 256; }
    else if (idx < 229376)  { W = Wo; hi = oh; lo = ol; N = 256; base = 163840; nofs = 0; }
    else if (idx < 229376 + 256) { bq[idx - 229376] = bs[idx - 229376]; return; }
    else if (idx < 229376 + 384) { bq[idx - 229376] = ba[idx - 229632]; return; }
    else return;
    int j = idx - base;
    int k = j / N, n = j % N + nofs;
    float v = W[j];
    __nv_bfloat16 h = __float2bfloat16(v);
    hi[n * 256 + k] = h;
    lo[n * 256 + k] = __float2bfloat16(v - __bfloat162float(h));
}

// ---------------------------------------------------------------------------
// Sampling kernel v3: fp16 value (halves L2 traffic), bf16-split output.
// block=query, warp=head; lane: cr=lane>>3 corner, e=lane&7 channel-group(4ch).
// ---------------------------------------------------------------------------
__global__ __launch_bounds__(256) void msda_sample(
    const __half* __restrict__ value,    // [Lq,256] fp16
    const float* __restrict__ qout,      // [Lq,384] offsets|logits
    const float* __restrict__ rp,        // [Lq,4,2]
    __nv_bfloat16* __restrict__ acch,
    __nv_bfloat16* __restrict__ accl)
{
    constexpr int HH[4] = {180, 90, 45, 23};
    constexpr int WW[4] = {180, 90, 45, 23};
    constexpr int ST[4] = {0, 32400, 40500, 42525};

    const int q = blockIdx.x;
    const int h = threadIdx.x >> 5;
    const int lane = threadIdx.x & 31;
    const int cr = lane >> 3;
    const int e  = lane & 7;

    // softmax over this head's 16 logits
    float lg = -1e30f;
    if (lane < 16) lg = qout[q * 384 + 256 + h * 16 + lane];
    float m = lg;
#pragma unroll
    for (int s = 16; s > 0; s >>= 1)
        m = fmaxf(m, __shfl_xor_sync(0xffffffffu, m, s));
    float eo = (lane < 16) ? __expf(lg - m) : 0.f;
    float ssum = eo;
#pragma unroll
    for (int s = 16; s > 0; s >>= 1)
        ssum += __shfl_xor_sync(0xffffffffu, ssum, s);
    const float aw = eo / ssum;

    // geometry lanes: continuous sample position per (level,point)
    float gx = 0.f, gy = 0.f;
    if (lane < 16) {
        const int l = lane >> 2;
        const int p = lane & 3;
        const int Hl = HH[l], Wl = WW[l];
        const float rx = rp[(q * 4 + l) * 2 + 0];
        const float ry = rp[(q * 4 + l) * 2 + 1];
        const int oj = q * 384 + (((h * 4 + l) * 4) + p) * 2;
        gx = fmaf(rx, (float)Wl, qout[oj + 0]) - 0.5f;
        gy = fmaf(ry, (float)Hl, qout[oj + 1]) - 0.5f;
    }

    const char* vbase = (const char*)value + h * 64 + e * 8;  // bytes
    float4 acc = make_float4(0.f, 0.f, 0.f, 0.f);
    const int cx1 = cr & 1, cy1 = cr >> 1;

#pragma unroll
    for (int i = 0; i < 16; i++) {
        const int l = i >> 2;
        const int Hl = HH[l], Wl = WW[l], st = ST[l];
        const float x = __shfl_sync(0xffffffffu, gx, i);
        const float y = __shfl_sync(0xffffffffu, gy, i);
        const float w0 = __shfl_sync(0xffffffffu, aw, i);

        const float xf = floorf(x), yf = floorf(y);
        const float dx = x - xf, dy = y - yf;
        const int xi = (int)xf + cx1;
        const int yi = (int)yf + cy1;
        const bool v = (xi >= 0) & (xi < Wl) & (yi >= 0) & (yi < Hl);
        const int cx = min(max(xi, 0), Wl - 1);
        const int cy = min(max(yi, 0), Hl - 1);
        const int idx = st + cy * Wl + cx;
        const float wx = cx1 ? dx : (1.f - dx);
        const float wy = cy1 ? dy : (1.f - dy);
        const float w = v ? w0 * wx * wy : 0.f;

        const uint2 raw = *(const uint2*)(vbase + (size_t)idx * 512);
        const float2 f0 = __half22float2(*(const __half2*)&raw.x);
        const float2 f1 = __half22float2(*(const __half2*)&raw.y);
        acc.x = fmaf(w, f0.x, acc.x);
        acc.y = fmaf(w, f0.y, acc.y);
        acc.z = fmaf(w, f1.x, acc.z);
        acc.w = fmaf(w, f1.y, acc.w);
    }

    // reduce over 4 corner groups
#pragma unroll
    for (int s = 8; s <= 16; s <<= 1) {
        acc.x += __shfl_xor_sync(0xffffffffu, acc.x, s);
        acc.y += __shfl_xor_sync(0xffffffffu, acc.y, s);
        acc.z += __shfl_xor_sync(0xffffffffu, acc.z, s);
        acc.w += __shfl_xor_sync(0xffffffffu, acc.w, s);
    }
    if (lane < 8) {
        float vals[4] = {acc.x, acc.y, acc.z, acc.w};
        uint32_t hiw[2], low[2];
#pragma unroll
        for (int i = 0; i < 2; i++) {
            float a0 = vals[2 * i], a1 = vals[2 * i + 1];
            __nv_bfloat16 h0 = __float2bfloat16(a0);
            __nv_bfloat16 h1 = __float2bfloat16(a1);
            hiw[i] = packbf2(a0, a1);
            low[i] = packbf2(a0 - __bfloat162float(h0),
                             a1 - __bfloat162float(h1));
        }
        const size_t o = (size_t)q * 256 + h * 32 + lane * 4;
        *(uint2*)&acch[o] = make_uint2(hiw[0], hiw[1]);
        *(uint2*)&accl[o] = make_uint2(low[0], low[1]);
    }
}

// ---------------------------------------------------------------------------
// Launch
// ---------------------------------------------------------------------------
extern "C" void kernel_launch(void* const* d_in, const int* in_sizes, int n_in,
                              void* d_out, int out_size)
{
    const float* query    = (const float*)d_in[0];
    const float* value_in = (const float*)d_in[1];
    const float* rp       = (const float*)d_in[2];
    const float* Wv       = (const float*)d_in[3];
    const float* bv       = (const float*)d_in[4];
    const float* Ws       = (const float*)d_in[5];
    const float* bs       = (const float*)d_in[6];
    const float* Wa       = (const float*)d_in[7];
    const float* ba       = (const float*)d_in[8];
    const float* Wo       = (const float*)d_in[9];
    const float* bo       = (const float*)d_in[10];
    float* out = (float*)d_out;

    __half* pvh;
    float *pq, *pbq;
    __nv_bfloat16 *pah, *pal;
    cudaGetSymbolAddress((void**)&pvh, g_value_h);
    cudaGetSymbolAddress((void**)&pq,  g_qout);
    cudaGetSymbolAddress((void**)&pah, g_acch);
    cudaGetSymbolAddress((void**)&pal, g_accl);
    cudaGetSymbolAddress((void**)&pbq, g_bq);
    __nv_bfloat16 *wvh, *wvl, *wqh, *wql, *woh, *wol;
    cudaGetSymbolAddress((void**)&wvh, g_Wvh);
    cudaGetSymbolAddress((void**)&wvl, g_Wvl);
    cudaGetSymbolAddress((void**)&wqh, g_Wqh);
    cudaGetSymbolAddress((void**)&wql, g_Wql);
    cudaGetSymbolAddress((void**)&woh, g_Woh);
    cudaGetSymbolAddress((void**)&wol, g_Wol);

    const int SMEM = 65536;
    cudaFuncSetAttribute(gemm_mma<false, true>,  cudaFuncAttributeMaxDynamicSharedMemorySize, SMEM);
    cudaFuncSetAttribute(gemm_mma<false, false>, cudaFuncAttributeMaxDynamicSharedMemorySize, SMEM);
    cudaFuncSetAttribute(gemm_mma<true,  false>, cudaFuncAttributeMaxDynamicSharedMemorySize, SMEM);

    const int M = LQ;
    const int GBY = (M + 127) / 128;  // 337
    dim3 blk(256);

    // Weight prep (single launch)
    prep_weights<<<(229376 + 384 + 255) / 256, 256>>>(Wv, Ws, Wa, Wo, bs, ba,
                                                      wvh, wvl, wqh, wql, woh, wol, pbq);

    // value projection -> fp16
    gemm_mma<false, true><<<dim3(2, GBY), blk, SMEM>>>(
        value_in, nullptr, nullptr, wvh, wvl, bv, nullptr, pvh, M, 256);
    // merged offsets+logits projection (N=384)
    gemm_mma<false, false><<<dim3(3, GBY), blk, SMEM>>>(
        query, nullptr, nullptr, wqh, wql, pbq, pq, nullptr, M, 384);

    // Deformable sampling (outputs pre-split bf16)
    msda_sample<<<M, 256>>>(pvh, pq, rp, pah, pal);

    // Output projection (A pre-split)
    gemm_mma<true, false><<<dim3(2, GBY), blk, SMEM>>>(
        nullptr, pah, pal, woh, wol, bo, out, nullptr, M, 256);
}

// round 6
// speedup vs baseline: 1.8119x; 1.1394x over previous
#include <cuda_runtime.h>
#include <cuda_bf16.h>
#include <cuda_fp16.h>
#include <cstdint>

// Problem constants
#define LQ      43054
#define NHEADS  8

// Padded value geometry: each level padded +2 on every side.
// L0 180x180 -> 184x184 (base 0),     L1 90x90 -> 94x94 (base 33856)
// L2 45x45   -> 49x49   (base 42692), L3 23x23 -> 27x27 (base 45093)
#define PADROWS 45822

// Scratch (device globals; no runtime allocation allowed)
__device__ __half g_value_h[PADROWS * 256];     // projected value, fp16, PADDED
__device__ float  g_qout[LQ * 384];             // [0,256)=offsets, [256,384)=logits
__device__ __nv_bfloat16 g_acch[LQ * 256];      // msda out hi
__device__ __nv_bfloat16 g_accl[LQ * 256];      // msda out lo
// pre-transposed + split weights: [N, 256] K-major, bf16 hi/lo
__device__ __nv_bfloat16 g_Wvh[256 * 256], g_Wvl[256 * 256];
__device__ __nv_bfloat16 g_Wqh[384 * 256], g_Wql[384 * 256];   // merged Ws|Wa
__device__ __nv_bfloat16 g_Woh[256 * 256], g_Wol[256 * 256];
__device__ float g_bq[384];                     // merged bias bs|ba

#define SW128(o) ((o) ^ (((o) >> 3) & 0x70))

__device__ __forceinline__ uint32_t smem_u32(const void* p) {
    uint32_t a;
    asm("{ .reg .u64 t; cvta.to.shared.u64 t, %1; cvt.u32.u64 %0, t; }" : "=r"(a) : "l"(p));
    return a;
}
__device__ __forceinline__ void ldsm4(uint32_t r[4], uint32_t addr) {
    asm volatile("ldmatrix.sync.aligned.m8n8.x4.shared.b16 {%0,%1,%2,%3}, [%4];"
        : "=r"(r[0]), "=r"(r[1]), "=r"(r[2]), "=r"(r[3]) : "r"(addr));
}
__device__ __forceinline__ void mma_bf16(float d[4], const uint32_t a[4],
                                         uint32_t b0, uint32_t b1) {
    asm volatile("mma.sync.aligned.m16n8k16.row.col.f32.bf16.bf16.f32 "
        "{%0,%1,%2,%3}, {%4,%5,%6,%7}, {%8,%9}, {%0,%1,%2,%3};"
        : "+f"(d[0]), "+f"(d[1]), "+f"(d[2]), "+f"(d[3])
        : "r"(a[0]), "r"(a[1]), "r"(a[2]), "r"(a[3]), "r"(b0), "r"(b1));
}
__device__ __forceinline__ uint32_t packbf2(float x, float y) {
    __nv_bfloat162 h = __floats2bfloat162_rn(x, y);
    return *(uint32_t*)&h;
}
__device__ __forceinline__ void cpa16(uint32_t d, const void* s) {
    asm volatile("cp.async.cg.shared.global [%0], [%1], 16;" :: "r"(d), "l"(s));
}
__device__ __forceinline__ void cpa16z(uint32_t d, const void* s, int srcsz) {
    asm volatile("cp.async.cg.shared.global [%0], [%1], 16, %2;" :: "r"(d), "l"(s), "r"(srcsz));
}
#define CP_COMMIT() asm volatile("cp.async.commit_group;" ::: "memory")
template <int Ngrp>
__device__ __forceinline__ void cp_wait() {
    asm volatile("cp.async.wait_group %0;" :: "n"(Ngrp) : "memory");
}

// Map original value row -> padded row index (compile-time divisors).
__device__ __forceinline__ int pad_row(int r) {
    if (r < 32400) { int cy = r / 180, cx = r - cy * 180; return (cy + 2) * 184 + cx + 2; }
    if (r < 40500) { int rr = r - 32400; int cy = rr / 90, cx = rr - cy * 90; return 33856 + (cy + 2) * 94 + cx + 2; }
    if (r < 42525) { int rr = r - 40500; int cy = rr / 45, cx = rr - cy * 45; return 42692 + (cy + 2) * 49 + cx + 2; }
    { int rr = r - 42525; int cy = rr / 23, cx = rr - cy * 23; return 45093 + (cy + 2) * 27 + cx + 2; }
}

// ---------------------------------------------------------------------------
// Zero the padding borders of g_value_h (1.4 MB) each call.
// ---------------------------------------------------------------------------
__global__ __launch_bounds__(256) void zero_pads(__half* __restrict__ vp) {
    int idx = blockIdx.x * 256 + threadIdx.x;
    if (idx >= PADROWS * 16) return;
    int row = idx >> 4, c = idx & 15;
    bool pad;
    if (row < 33856)      { int py = row / 184, px = row - py * 184;
                            pad = (py < 2) | (py >= 182) | (px < 2) | (px >= 182); }
    else if (row < 42692) { int r2 = row - 33856; int py = r2 / 94, px = r2 - py * 94;
                            pad = (py < 2) | (py >= 92) | (px < 2) | (px >= 92); }
    else if (row < 45093) { int r2 = row - 42692; int py = r2 / 49, px = r2 - py * 49;
                            pad = (py < 2) | (py >= 47) | (px < 2) | (px >= 47); }
    else                  { int r2 = row - 45093; int py = r2 / 27, px = r2 - py * 27;
                            pad = (py < 2) | (py >= 25) | (px < 2) | (px >= 25); }
    if (pad) {
        uint4* d = (uint4*)((char*)vp + (size_t)row * 512 + c * 32);
        d[0] = make_uint4(0, 0, 0, 0);
        d[1] = make_uint4(0, 0, 0, 0);
    }
}

// ---------------------------------------------------------------------------
// Tensor-core GEMM, bf16 split-3, cp.async-pipelined.
//   C[M,N] = A[M,256] @ W[256,N] + bias
// ASPLIT=false: A fp32 (register-staged + converted); B via cp.async (4 groups).
// ASPLIT=true : A pre-split bf16 via cp.async (double-buffered) + B cp.async.
// OUTHALF: write C as fp16 into PADDED value layout.
// CTA 128x128, 256 thr, 8 warps (4m x 2n), K chunks of 64.
// ---------------------------------------------------------------------------
template <bool ASPLIT, bool OUTHALF>
__global__ __launch_bounds__(256) void gemm_mma(
    const float* __restrict__ A,
    const __nv_bfloat16* __restrict__ AhG,
    const __nv_bfloat16* __restrict__ AlG,
    const __nv_bfloat16* __restrict__ Bh,
    const __nv_bfloat16* __restrict__ Bl,
    const float* __restrict__ bias,
    float* __restrict__ C,
    __half* __restrict__ Ch,
    int M, int N)
{
    extern __shared__ char smem[];
    const uint32_t sb = smem_u32(smem);
    // A region: ASPLIT -> 2 bufs x (hi16K+lo16K) = 64KB; else 1 buf = 32KB.
    constexpr int BBASE = ASPLIT ? 65536 : 32768;   // B chunks: 4 x (hi16K+lo16K)

    const int tid = threadIdx.x;
    const int wid = tid >> 5, lane = tid & 31;
    const int wm = (wid & 3) * 32;
    const int wn = (wid >> 2) * 64;
    const int bm = blockIdx.y * 128;
    const int bn = blockIdx.x * 128;

    float acc[2][8][4];
#pragma unroll
    for (int i = 0; i < 2; i++)
#pragma unroll
        for (int j = 0; j < 8; j++)
#pragma unroll
            for (int k = 0; k < 4; k++) acc[i][j][k] = 0.f;

    const int a_row = lane & 15;
    const int a_k8  = (lane >> 4) << 3;
    const int b_row = (lane & 7) + ((lane & 16) >> 1);
    const int b_k8  = lane & 8;

    const int ld_row = tid >> 1;          // 0..127
    const int ld_kh  = (tid & 1) * 32;    // 0 or 32 (k elements)
    const int grow   = bm + ld_row;
    const bool okA   = grow < M;

    // ---- async B chunk issue
    auto issueB = [&](int c) {
        const int k0 = c * 64;
        const int n = bn + ld_row;
        const __nv_bfloat16* sH = &Bh[(size_t)n * 256 + k0 + ld_kh];
        const __nv_bfloat16* sL = &Bl[(size_t)n * 256 + k0 + ld_kh];
        const uint32_t basH = sb + BBASE + c * 32768;
        const uint32_t basL = basH + 16384;
#pragma unroll
        for (int jj = 0; jj < 4; jj++) {
            uint32_t off = SW128((uint32_t)(ld_row * 128 + (ld_kh + jj * 8) * 2));
            cpa16(basH + off, sH + jj * 8);
            cpa16(basL + off, sL + jj * 8);
        }
    };
    // ---- async A chunk issue (ASPLIT only), buf = c&1
    auto issueA = [&](int c) {
        const int k0 = c * 64;
        const uint32_t basH = sb + (c & 1) * 32768;
        const uint32_t basL = basH + 16384;
        const __nv_bfloat16* sH = &AhG[(size_t)grow * 256 + k0 + ld_kh];
        const __nv_bfloat16* sL = &AlG[(size_t)grow * 256 + k0 + ld_kh];
        const int sz = okA ? 16 : 0;
#pragma unroll
        for (int jj = 0; jj < 4; jj++) {
            uint32_t off = SW128((uint32_t)(ld_row * 128 + (ld_kh + jj * 8) * 2));
            cpa16z(basH + off, sH + jj * 8, sz);
            cpa16z(basL + off, sL + jj * 8, sz);
        }
    };

    // ---- fp32 A register stage + convert/commit (!ASPLIT)
    float4 vA[8];
    auto stageA = [&](int c) {
        const int k0 = c * 64;
        const float4* src = (const float4*)&A[(size_t)(okA ? grow : 0) * 256 + k0 + ld_kh];
#pragma unroll
        for (int j = 0; j < 8; j++)
            vA[j] = okA ? src[j] : make_float4(0.f, 0.f, 0.f, 0.f);
    };
    auto commitA = [&]() {
#pragma unroll
        for (int jj = 0; jj < 4; jj++) {
            float4 v0 = vA[jj * 2 + 0];
            float4 v1 = vA[jj * 2 + 1];
            float vs[8] = {v0.x, v0.y, v0.z, v0.w, v1.x, v1.y, v1.z, v1.w};
            uint4 hi4, lo4;
            uint32_t* hp = (uint32_t*)&hi4;
            uint32_t* lp = (uint32_t*)&lo4;
#pragma unroll
            for (int i = 0; i < 4; i++) {
                float a0 = vs[2 * i], a1 = vs[2 * i + 1];
                __nv_bfloat16 h0 = __float2bfloat16(a0);
                __nv_bfloat16 h1 = __float2bfloat16(a1);
                hp[i] = packbf2(a0, a1);
                lp[i] = packbf2(a0 - __bfloat162float(h0),
                                a1 - __bfloat162float(h1));
            }
            uint32_t off = SW128((uint32_t)(ld_row * 128 + (ld_kh + jj * 8) * 2));
            *(uint4*)(smem + off) = hi4;            // A hi at 0
            *(uint4*)(smem + 16384 + off) = lo4;    // A lo at 16K
        }
    };

    // ---- MMA over one 64-k chunk
    auto mma_chunk = [&](uint32_t aH, uint32_t aL, uint32_t bH, uint32_t bL) {
#pragma unroll
        for (int ks = 0; ks < 4; ks++) {
            uint32_t ah[2][4], al[2][4];
#pragma unroll
            for (int mt = 0; mt < 2; mt++) {
                uint32_t aoff = SW128((uint32_t)((wm + mt * 16 + a_row) * 128 +
                                                 (ks * 16 + a_k8) * 2));
                ldsm4(ah[mt], aH + aoff);
                ldsm4(al[mt], aL + aoff);
            }
#pragma unroll
            for (int ng = 0; ng < 4; ng++) {
                uint32_t boff = SW128((uint32_t)((wn + ng * 16 + b_row) * 128 +
                                                 (ks * 16 + b_k8) * 2));
                uint32_t bh4[4], bl4[4];
                ldsm4(bh4, bH + boff);
                ldsm4(bl4, bL + boff);
#pragma unroll
                for (int mt = 0; mt < 2; mt++) {
                    mma_bf16(acc[mt][ng * 2 + 0], ah[mt], bh4[0], bh4[1]);
                    mma_bf16(acc[mt][ng * 2 + 0], al[mt], bh4[0], bh4[1]);
                    mma_bf16(acc[mt][ng * 2 + 0], ah[mt], bl4[0], bl4[1]);
                    mma_bf16(acc[mt][ng * 2 + 1], ah[mt], bh4[2], bh4[3]);
                    mma_bf16(acc[mt][ng * 2 + 1], al[mt], bh4[2], bh4[3]);
                    mma_bf16(acc[mt][ng * 2 + 1], ah[mt], bl4[2], bl4[3]);
                }
            }
        }
    };

    if (ASPLIT) {
        issueB(0); issueA(0); CP_COMMIT();   // g0
        issueB(1); issueA(1); CP_COMMIT();   // g1
        issueB(2); CP_COMMIT();              // g2
        issueB(3); CP_COMMIT();              // g3
#pragma unroll
        for (int c = 0; c < 4; c++) {
            if (c == 0) cp_wait<3>();
            else if (c == 1) cp_wait<3>();
            else if (c == 2) cp_wait<1>();
            else cp_wait<0>();
            __syncthreads();
            mma_chunk(sb + (c & 1) * 32768, sb + (c & 1) * 32768 + 16384,
                      sb + BBASE + c * 32768, sb + BBASE + c * 32768 + 16384);
            if (c < 2) {
                __syncthreads();
                issueA(c + 2); CP_COMMIT();  // g4, g5
            }
        }
    } else {
        issueB(0); CP_COMMIT();
        issueB(1); CP_COMMIT();
        issueB(2); CP_COMMIT();
        issueB(3); CP_COMMIT();
        stageA(0);
#pragma unroll
        for (int c = 0; c < 4; c++) {
            if (c > 0) __syncthreads();      // prior MMA done before A overwrite
            commitA();
            if (c < 3) stageA(c + 1);
            if (c == 0) cp_wait<3>();
            else if (c == 1) cp_wait<2>();
            else if (c == 2) cp_wait<1>();
            else cp_wait<0>();
            __syncthreads();
            mma_chunk(sb, sb + 16384,
                      sb + BBASE + c * 32768, sb + BBASE + c * 32768 + 16384);
        }
    }

    // ---- epilogue
    const int g = lane >> 2;
    const int cbase = bn + wn + (lane & 3) * 2;
    int prow[2][2];
    if (OUTHALF) {
#pragma unroll
        for (int mt = 0; mt < 2; mt++) {
            int r0 = bm + wm + mt * 16 + g;
            prow[mt][0] = (r0 < M) ? pad_row(r0) : 0;
            prow[mt][1] = (r0 + 8 < M) ? pad_row(r0 + 8) : 0;
        }
    }
#pragma unroll
    for (int nt = 0; nt < 8; nt++) {
        const int col = cbase + nt * 8;
        const float b0 = bias[col], b1 = bias[col + 1];
#pragma unroll
        for (int mt = 0; mt < 2; mt++) {
            int r0 = bm + wm + mt * 16 + g;
            if (r0 < M) {
                if (OUTHALF) {
                    __half2 hv = __floats2half2_rn(acc[mt][nt][0] + b0, acc[mt][nt][1] + b1);
                    *(__half2*)&Ch[(size_t)prow[mt][0] * 256 + col] = hv;
                } else {
                    *(float2*)&C[(size_t)r0 * N + col] =
                        make_float2(acc[mt][nt][0] + b0, acc[mt][nt][1] + b1);
                }
            }
            int r1 = r0 + 8;
            if (r1 < M) {
                if (OUTHALF) {
                    __half2 hv = __floats2half2_rn(acc[mt][nt][2] + b0, acc[mt][nt][3] + b1);
                    *(__half2*)&Ch[(size_t)prow[mt][1] * 256 + col] = hv;
                } else {
                    *(float2*)&C[(size_t)r1 * N + col] =
                        make_float2(acc[mt][nt][2] + b0, acc[mt][nt][3] + b1);
                }
            }
        }
    }
}

// ---------------------------------------------------------------------------
// Weight prep (single launch): Wv, merged Ws|Wa, Wo; merged bias.
// ---------------------------------------------------------------------------
__global__ void prep_weights(const float* __restrict__ Wv,
                             const float* __restrict__ Ws,
                             const float* __restrict__ Wa,
                             const float* __restrict__ Wo,
                             const float* __restrict__ bs,
                             const float* __restrict__ ba,
                             __nv_bfloat16* __restrict__ vh, __nv_bfloat16* __restrict__ vl,
                             __nv_bfloat16* __restrict__ qh, __nv_bfloat16* __restrict__ ql,
                             __nv_bfloat16* __restrict__ oh, __nv_bfloat16* __restrict__ ol,
                             float* __restrict__ bq)
{
    int idx = blockIdx.x * 256 + threadIdx.x;
    const float* W;
    __nv_bfloat16 *hi, *lo;
    int N, base, nofs;
    if (idx < 65536)        { W = Wv; hi = vh; lo = vl; N = 256; base = 0;      nofs = 0; }
    else if (idx < 131072)  { W = Ws; hi = qh; lo = ql; N = 256; base = 65536;  nofs = 0; }
    else if (idx < 163840)  { W = Wa; hi = qh; lo = ql; N = 128; base = 131072; nofs = 256; }
    else if (idx < 229376)  { W = Wo; hi = oh; lo = ol; N = 256; base = 163840; nofs = 0; }
    else if (idx < 229376 + 256) { bq[idx - 229376] = bs[idx - 229376]; return; }
    else if (idx < 229376 + 384) { bq[idx - 229376] = ba[idx - 229632]; return; }
    else return;
    int j = idx - base;
    int k = j / N, n = j % N + nofs;
    float v = W[j];
    __nv_bfloat16 h = __float2bfloat16(v);
    hi[n * 256 + k] = h;
    lo[n * 256 + k] = __float2bfloat16(v - __bfloat162float(h));
}

// ---------------------------------------------------------------------------
// Sampling kernel v4: padded value -> no bounds/clamp/index math in loop.
// block=query, warp=head; lane: cr=lane>>3 corner, e=lane&7 channel-group.
// ---------------------------------------------------------------------------
__global__ __launch_bounds__(256) void msda_sample(
    const __half* __restrict__ value,    // PADDED [45822,256] fp16
    const float* __restrict__ qout,      // [Lq,384] offsets|logits
    const float* __restrict__ rp,        // [Lq,4,2]
    __nv_bfloat16* __restrict__ acch,
    __nv_bfloat16* __restrict__ accl)
{
    constexpr int WW[4] = {180, 90, 45, 23};
    constexpr int PB[4] = {0, 33856, 42692, 45093};

    const int q = blockIdx.x;
    const int h = threadIdx.x >> 5;
    const int lane = threadIdx.x & 31;
    const int cr = lane >> 3;
    const int e  = lane & 7;
    const int cx1 = cr & 1, cy1 = cr >> 1;

    // softmax over this head's 16 logits
    float lg = -1e30f;
    if (lane < 16) lg = qout[q * 384 + 256 + h * 16 + lane];
    float m = lg;
#pragma unroll
    for (int s = 16; s > 0; s >>= 1)
        m = fmaxf(m, __shfl_xor_sync(0xffffffffu, m, s));
    float eo = (lane < 16) ? __expf(lg - m) : 0.f;
    float ssum = eo;
#pragma unroll
    for (int s = 16; s > 0; s >>= 1)
        ssum += __shfl_xor_sync(0xffffffffu, ssum, s);
    const float aw = eo / ssum;

    // geometry lanes: base byte address + premultiplied weights
    int   Gbase = 0;
    float Gadx = 0.f, Ga1x = 0.f, Gdy = 0.f;
    if (lane < 16) {
        const int l = lane >> 2;
        const int p = lane & 3;
        const int W = WW[l];
        const float rx = rp[(q * 4 + l) * 2 + 0];
        const float ry = rp[(q * 4 + l) * 2 + 1];
        const int oj = q * 384 + (((h * 4 + l) * 4) + p) * 2;
        const float x = fmaf(rx, (float)W, qout[oj + 0]) - 0.5f;
        const float y = fmaf(ry, (float)W, qout[oj + 1]) - 0.5f;
        const float xf = floorf(x), yf = floorf(y);
        const float dx = x - xf, dy = y - yf;
        const int xc = min(max((int)xf, -2), W);
        const int yc = min(max((int)yf, -2), W);
        Gbase = (PB[l] + (yc + 2) * (W + 4) + (xc + 2)) * 512;
        Gadx = aw * dx;
        Ga1x = aw - Gadx;
        Gdy  = dy;
    }
    int cstep[4];
#pragma unroll
    for (int l = 0; l < 4; l++)
        cstep[l] = (cy1 * (WW[l] + 4) + cx1) * 512;

    const char* __restrict__ vb = (const char*)value + h * 64 + e * 8;
    float4 acc = make_float4(0.f, 0.f, 0.f, 0.f);

#pragma unroll
    for (int i = 0; i < 16; i++) {
        const int l = i >> 2;   // compile-time
        const int   b   = __shfl_sync(0xffffffffu, Gbase, i);
        const float adx = __shfl_sync(0xffffffffu, Gadx, i);
        const float a1x = __shfl_sync(0xffffffffu, Ga1x, i);
        const float dyv = __shfl_sync(0xffffffffu, Gdy, i);
        const float wxa = cx1 ? adx : a1x;
        const float wy  = cy1 ? dyv : (1.f - dyv);
        const float w   = wxa * wy;

        const uint2 raw = *(const uint2*)(vb + (size_t)(uint32_t)(b + cstep[l]));
        const float2 f0 = __half22float2(*(const __half2*)&raw.x);
        const float2 f1 = __half22float2(*(const __half2*)&raw.y);
        acc.x = fmaf(w, f0.x, acc.x);
        acc.y = fmaf(w, f0.y, acc.y);
        acc.z = fmaf(w, f1.x, acc.z);
        acc.w = fmaf(w, f1.y, acc.w);
    }

    // reduce over 4 corner groups
#pragma unroll
    for (int s = 8; s <= 16; s <<= 1) {
        acc.x += __shfl_xor_sync(0xffffffffu, acc.x, s);
        acc.y += __shfl_xor_sync(0xffffffffu, acc.y, s);
        acc.z += __shfl_xor_sync(0xffffffffu, acc.z, s);
        acc.w += __shfl_xor_sync(0xffffffffu, acc.w, s);
    }
    if (lane < 8) {
        float vals[4] = {acc.x, acc.y, acc.z, acc.w};
        uint32_t hiw[2], low[2];
#pragma unroll
        for (int i = 0; i < 2; i++) {
            float a0 = vals[2 * i], a1 = vals[2 * i + 1];
            __nv_bfloat16 h0 = __float2bfloat16(a0);
            __nv_bfloat16 h1 = __float2bfloat16(a1);
            hiw[i] = packbf2(a0, a1);
            low[i] = packbf2(a0 - __bfloat162float(h0),
                             a1 - __bfloat162float(h1));
        }
        const size_t o = (size_t)q * 256 + h * 32 + lane * 4;
        *(uint2*)&acch[o] = make_uint2(hiw[0], hiw[1]);
        *(uint2*)&accl[o] = make_uint2(low[0], low[1]);
    }
}

// ---------------------------------------------------------------------------
// Launch
// ---------------------------------------------------------------------------
extern "C" void kernel_launch(void* const* d_in, const int* in_sizes, int n_in,
                              void* d_out, int out_size)
{
    const float* query    = (const float*)d_in[0];
    const float* value_in = (const float*)d_in[1];
    const float* rp       = (const float*)d_in[2];
    const float* Wv       = (const float*)d_in[3];
    const float* bv       = (const float*)d_in[4];
    const float* Ws       = (const float*)d_in[5];
    const float* bs       = (const float*)d_in[6];
    const float* Wa       = (const float*)d_in[7];
    const float* ba       = (const float*)d_in[8];
    const float* Wo       = (const float*)d_in[9];
    const float* bo       = (const float*)d_in[10];
    float* out = (float*)d_out;

    __half* pvh;
    float *pq, *pbq;
    __nv_bfloat16 *pah, *pal;
    cudaGetSymbolAddress((void**)&pvh, g_value_h);
    cudaGetSymbolAddress((void**)&pq,  g_qout);
    cudaGetSymbolAddress((void**)&pah, g_acch);
    cudaGetSymbolAddress((void**)&pal, g_accl);
    cudaGetSymbolAddress((void**)&pbq, g_bq);
    __nv_bfloat16 *wvh, *wvl, *wqh, *wql, *woh, *wol;
    cudaGetSymbolAddress((void**)&wvh, g_Wvh);
    cudaGetSymbolAddress((void**)&wvl, g_Wvl);
    cudaGetSymbolAddress((void**)&wqh, g_Wqh);
    cudaGetSymbolAddress((void**)&wql, g_Wql);
    cudaGetSymbolAddress((void**)&woh, g_Woh);
    cudaGetSymbolAddress((void**)&wol, g_Wol);

    const int SMEM_F = 32768 + 131072;   // !ASPLIT: 160KB
    const int SMEM_T = 65536 + 131072;   // ASPLIT:  192KB
    cudaFuncSetAttribute(gemm_mma<false, true>,  cudaFuncAttributeMaxDynamicSharedMemorySize, SMEM_F);
    cudaFuncSetAttribute(gemm_mma<false, false>, cudaFuncAttributeMaxDynamicSharedMemorySize, SMEM_F);
    cudaFuncSetAttribute(gemm_mma<true,  false>, cudaFuncAttributeMaxDynamicSharedMemorySize, SMEM_T);

    const int M = LQ;
    const int GBY = (M + 127) / 128;  // 337
    dim3 blk(256);

    // Zero padded borders + weight prep
    zero_pads<<<(PADROWS * 16 + 255) / 256, 256>>>(pvh);
    prep_weights<<<(229376 + 384 + 255) / 256, 256>>>(Wv, Ws, Wa, Wo, bs, ba,
                                                      wvh, wvl, wqh, wql, woh, wol, pbq);

    // value projection -> fp16 padded layout
    gemm_mma<false, true><<<dim3(2, GBY), blk, SMEM_F>>>(
        value_in, nullptr, nullptr, wvh, wvl, bv, nullptr, pvh, M, 256);
    // merged offsets+logits projection (N=384)
    gemm_mma<false, false><<<dim3(3, GBY), blk, SMEM_F>>>(
        query, nullptr, nullptr, wqh, wql, pbq, pq, nullptr, M, 384);

    // Deformable sampling (padded gather, pre-split bf16 out)
    msda_sample<<<M, 256>>>(pvh, pq, rp, pah, pal);

    // Output projection (A pre-split, fully async loads)
    gemm_mma<true, false><<<dim3(2, GBY), blk, SMEM_T>>>(
        nullptr, pah, pal, woh, wol, bo, out, nullptr, M, 256);
}

// round 7
// speedup vs baseline: 1.9588x; 1.0811x over previous
#include <cuda_runtime.h>
#include <cuda_bf16.h>
#include <cuda_fp16.h>
#include <cstdint>

// Problem constants
#define LQ      43054
#define NHEADS  8

// Padded value geometry: each level padded +2 on every side.
// L0 180x180 -> 184x184 (base 0),     L1 90x90 -> 94x94 (base 33856)
// L2 45x45   -> 49x49   (base 42692), L3 23x23 -> 27x27 (base 45093)
#define PADROWS 45822

// Scratch (device globals; no runtime allocation allowed)
__device__ __half g_value_h[PADROWS * 256];     // projected value, fp16, PADDED
__device__ float  g_qout[LQ * 384];             // [0,256)=offsets, [256,384)=logits
__device__ __nv_bfloat16 g_acch[LQ * 256];      // msda out hi
__device__ __nv_bfloat16 g_accl[LQ * 256];      // msda out lo
// pre-transposed + split weights: [N, 256] K-major, bf16 hi/lo
__device__ __nv_bfloat16 g_Wvh[256 * 256], g_Wvl[256 * 256];
__device__ __nv_bfloat16 g_Wqh[384 * 256], g_Wql[384 * 256];   // merged Ws|Wa
__device__ __nv_bfloat16 g_Woh[256 * 256], g_Wol[256 * 256];
__device__ float g_bq[384];                     // merged bias bs|ba

#define SW128(o) ((o) ^ (((o) >> 3) & 0x70))

__device__ __forceinline__ uint32_t smem_u32(const void* p) {
    uint32_t a;
    asm("{ .reg .u64 t; cvta.to.shared.u64 t, %1; cvt.u32.u64 %0, t; }" : "=r"(a) : "l"(p));
    return a;
}
__device__ __forceinline__ void ldsm4(uint32_t r[4], uint32_t addr) {
    asm volatile("ldmatrix.sync.aligned.m8n8.x4.shared.b16 {%0,%1,%2,%3}, [%4];"
        : "=r"(r[0]), "=r"(r[1]), "=r"(r[2]), "=r"(r[3]) : "r"(addr));
}
__device__ __forceinline__ void mma_bf16(float d[4], const uint32_t a[4],
                                         uint32_t b0, uint32_t b1) {
    asm volatile("mma.sync.aligned.m16n8k16.row.col.f32.bf16.bf16.f32 "
        "{%0,%1,%2,%3}, {%4,%5,%6,%7}, {%8,%9}, {%0,%1,%2,%3};"
        : "+f"(d[0]), "+f"(d[1]), "+f"(d[2]), "+f"(d[3])
        : "r"(a[0]), "r"(a[1]), "r"(a[2]), "r"(a[3]), "r"(b0), "r"(b1));
}
__device__ __forceinline__ uint32_t packbf2(float x, float y) {
    __nv_bfloat162 h = __floats2bfloat162_rn(x, y);
    return *(uint32_t*)&h;
}
__device__ __forceinline__ void cpa16(uint32_t d, const void* s) {
    asm volatile("cp.async.cg.shared.global [%0], [%1], 16;" :: "r"(d), "l"(s));
}
#define CP_COMMIT() asm volatile("cp.async.commit_group;" ::: "memory")
template <int Ngrp>
__device__ __forceinline__ void cp_wait() {
    asm volatile("cp.async.wait_group %0;" :: "n"(Ngrp) : "memory");
}

// Map original value row -> padded row index (compile-time divisors).
__device__ __forceinline__ int pad_row(int r) {
    if (r < 32400) { int cy = r / 180, cx = r - cy * 180; return (cy + 2) * 184 + cx + 2; }
    if (r < 40500) { int rr = r - 32400; int cy = rr / 90, cx = rr - cy * 90; return 33856 + (cy + 2) * 94 + cx + 2; }
    if (r < 42525) { int rr = r - 40500; int cy = rr / 45, cx = rr - cy * 45; return 42692 + (cy + 2) * 49 + cx + 2; }
    { int rr = r - 42525; int cy = rr / 23, cx = rr - cy * 23; return 45093 + (cy + 2) * 27 + cx + 2; }
}

// ---------------------------------------------------------------------------
// Zero the padding borders of g_value_h each call.
// ---------------------------------------------------------------------------
__global__ __launch_bounds__(256) void zero_pads(__half* __restrict__ vp) {
    int idx = blockIdx.x * 256 + threadIdx.x;
    if (idx >= PADROWS * 16) return;
    int row = idx >> 4, c = idx & 15;
    bool pad;
    if (row < 33856)      { int py = row / 184, px = row - py * 184;
                            pad = (py < 2) | (py >= 182) | (px < 2) | (px >= 182); }
    else if (row < 42692) { int r2 = row - 33856; int py = r2 / 94, px = r2 - py * 94;
                            pad = (py < 2) | (py >= 92) | (px < 2) | (px >= 92); }
    else if (row < 45093) { int r2 = row - 42692; int py = r2 / 49, px = r2 - py * 49;
                            pad = (py < 2) | (py >= 47) | (px < 2) | (px >= 47); }
    else                  { int r2 = row - 45093; int py = r2 / 27, px = r2 - py * 27;
                            pad = (py < 2) | (py >= 25) | (px < 2) | (px >= 25); }
    if (pad) {
        uint4* d = (uint4*)((char*)vp + (size_t)row * 512 + c * 32);
        d[0] = make_uint4(0, 0, 0, 0);
        d[1] = make_uint4(0, 0, 0, 0);
    }
}

// ---------------------------------------------------------------------------
// Tensor-core GEMM, bf16 split-3, 96KB smem -> 2 CTAs/SM.
//   C[M,N] = A[M,256] @ W[256,N] + bias
// A register-staged (fp32 converted in-kernel, or pre-split bf16).
// B double-buffered via cp.async, one chunk ahead.
// CTA 128x128, 256 thr, 8 warps (4m x 2n), K chunks of 64.
// smem: A hi 0..16K, A lo 16..32K, B bufs at 32K + (c&1)*32K.
// ---------------------------------------------------------------------------
template <bool ASPLIT, bool OUTHALF>
__global__ __launch_bounds__(256, 2) void gemm_mma(
    const float* __restrict__ A,
    const __nv_bfloat16* __restrict__ AhG,
    const __nv_bfloat16* __restrict__ AlG,
    const __nv_bfloat16* __restrict__ Bh,
    const __nv_bfloat16* __restrict__ Bl,
    const float* __restrict__ bias,
    float* __restrict__ C,
    __half* __restrict__ Ch,
    int M, int N)
{
    extern __shared__ char smem[];
    const uint32_t sb = smem_u32(smem);

    const int tid = threadIdx.x;
    const int wid = tid >> 5, lane = tid & 31;
    const int wm = (wid & 3) * 32;
    const int wn = (wid >> 2) * 64;
    const int bm = blockIdx.y * 128;
    const int bn = blockIdx.x * 128;

    float acc[2][8][4];
#pragma unroll
    for (int i = 0; i < 2; i++)
#pragma unroll
        for (int j = 0; j < 8; j++)
#pragma unroll
            for (int k = 0; k < 4; k++) acc[i][j][k] = 0.f;

    const int a_row = lane & 15;
    const int a_k8  = (lane >> 4) << 3;
    const int b_row = (lane & 7) + ((lane & 16) >> 1);
    const int b_k8  = lane & 8;

    const int ld_row = tid >> 1;          // 0..127
    const int ld_kh  = (tid & 1) * 32;    // 0 or 32 (k elements)
    const int grow   = bm + ld_row;
    const bool okA   = grow < M;

    // ---- async B chunk issue into buf (c&1)
    auto issueB = [&](int c) {
        const int k0 = c * 64;
        const int n = bn + ld_row;
        const __nv_bfloat16* sH = &Bh[(size_t)n * 256 + k0 + ld_kh];
        const __nv_bfloat16* sL = &Bl[(size_t)n * 256 + k0 + ld_kh];
        const uint32_t basH = sb + 32768 + (c & 1) * 32768;
        const uint32_t basL = basH + 16384;
#pragma unroll
        for (int jj = 0; jj < 4; jj++) {
            uint32_t off = SW128((uint32_t)(ld_row * 128 + (ld_kh + jj * 8) * 2));
            cpa16(basH + off, sH + jj * 8);
            cpa16(basL + off, sL + jj * 8);
        }
    };

    // ---- A register staging (both variants)
    float4 vA[8];       // !ASPLIT
    uint4  sAh[4], sAl[4];  // ASPLIT
    auto stageA = [&](int c) {
        const int k0 = c * 64;
        if (!ASPLIT) {
            const float4* src = (const float4*)&A[(size_t)(okA ? grow : 0) * 256 + k0 + ld_kh];
#pragma unroll
            for (int j = 0; j < 8; j++)
                vA[j] = okA ? src[j] : make_float4(0.f, 0.f, 0.f, 0.f);
        } else {
            const uint4* sh = (const uint4*)&AhG[(size_t)(okA ? grow : 0) * 256 + k0 + ld_kh];
            const uint4* sl = (const uint4*)&AlG[(size_t)(okA ? grow : 0) * 256 + k0 + ld_kh];
#pragma unroll
            for (int j = 0; j < 4; j++) {
                sAh[j] = okA ? sh[j] : make_uint4(0, 0, 0, 0);
                sAl[j] = okA ? sl[j] : make_uint4(0, 0, 0, 0);
            }
        }
    };
    auto commitA = [&]() {
        if (!ASPLIT) {
#pragma unroll
            for (int jj = 0; jj < 4; jj++) {
                float4 v0 = vA[jj * 2 + 0];
                float4 v1 = vA[jj * 2 + 1];
                float vs[8] = {v0.x, v0.y, v0.z, v0.w, v1.x, v1.y, v1.z, v1.w};
                uint4 hi4, lo4;
                uint32_t* hp = (uint32_t*)&hi4;
                uint32_t* lp = (uint32_t*)&lo4;
#pragma unroll
                for (int i = 0; i < 4; i++) {
                    float a0 = vs[2 * i], a1 = vs[2 * i + 1];
                    __nv_bfloat16 h0 = __float2bfloat16(a0);
                    __nv_bfloat16 h1 = __float2bfloat16(a1);
                    hp[i] = packbf2(a0, a1);
                    lp[i] = packbf2(a0 - __bfloat162float(h0),
                                    a1 - __bfloat162float(h1));
                }
                uint32_t off = SW128((uint32_t)(ld_row * 128 + (ld_kh + jj * 8) * 2));
                *(uint4*)(smem + off) = hi4;
                *(uint4*)(smem + 16384 + off) = lo4;
            }
        } else {
#pragma unroll
            for (int jj = 0; jj < 4; jj++) {
                uint32_t off = SW128((uint32_t)(ld_row * 128 + (ld_kh + jj * 8) * 2));
                *(uint4*)(smem + off) = sAh[jj];
                *(uint4*)(smem + 16384 + off) = sAl[jj];
            }
        }
    };

    // ---- MMA over one 64-k chunk
    auto mma_chunk = [&](uint32_t bH, uint32_t bL) {
#pragma unroll
        for (int ks = 0; ks < 4; ks++) {
            uint32_t ah[2][4], al[2][4];
#pragma unroll
            for (int mt = 0; mt < 2; mt++) {
                uint32_t aoff = SW128((uint32_t)((wm + mt * 16 + a_row) * 128 +
                                                 (ks * 16 + a_k8) * 2));
                ldsm4(ah[mt], sb + aoff);
                ldsm4(al[mt], sb + 16384 + aoff);
            }
#pragma unroll
            for (int ng = 0; ng < 4; ng++) {
                uint32_t boff = SW128((uint32_t)((wn + ng * 16 + b_row) * 128 +
                                                 (ks * 16 + b_k8) * 2));
                uint32_t bh4[4], bl4[4];
                ldsm4(bh4, bH + boff);
                ldsm4(bl4, bL + boff);
#pragma unroll
                for (int mt = 0; mt < 2; mt++) {
                    mma_bf16(acc[mt][ng * 2 + 0], ah[mt], bh4[0], bh4[1]);
                    mma_bf16(acc[mt][ng * 2 + 0], al[mt], bh4[0], bh4[1]);
                    mma_bf16(acc[mt][ng * 2 + 0], ah[mt], bl4[0], bl4[1]);
                    mma_bf16(acc[mt][ng * 2 + 1], ah[mt], bh4[2], bh4[3]);
                    mma_bf16(acc[mt][ng * 2 + 1], al[mt], bh4[2], bh4[3]);
                    mma_bf16(acc[mt][ng * 2 + 1], ah[mt], bl4[2], bl4[3]);
                }
            }
        }
    };

    // schedule: B0,B1 upfront; B(c+1) issued after sync retiring mma(c-1).
    issueB(0); CP_COMMIT();
    issueB(1); CP_COMMIT();
    stageA(0);
#pragma unroll
    for (int c = 0; c < 4; c++) {
        if (c > 0) {
            __syncthreads();                 // mma(c-1) done: A + B buf free
            if (c < 3) { issueB(c + 1); CP_COMMIT(); }
        }
        commitA();
        if (c < 3) stageA(c + 1);
        if (c < 3) cp_wait<1>(); else cp_wait<0>();
        __syncthreads();
        mma_chunk(sb + 32768 + (c & 1) * 32768,
                  sb + 32768 + (c & 1) * 32768 + 16384);
    }

    // ---- epilogue
    const int g = lane >> 2;
    const int cbase = bn + wn + (lane & 3) * 2;
    int prow[2][2];
    if (OUTHALF) {
#pragma unroll
        for (int mt = 0; mt < 2; mt++) {
            int r0 = bm + wm + mt * 16 + g;
            prow[mt][0] = (r0 < M) ? pad_row(r0) : 0;
            prow[mt][1] = (r0 + 8 < M) ? pad_row(r0 + 8) : 0;
        }
    }
#pragma unroll
    for (int nt = 0; nt < 8; nt++) {
        const int col = cbase + nt * 8;
        const float b0 = bias[col], b1 = bias[col + 1];
#pragma unroll
        for (int mt = 0; mt < 2; mt++) {
            int r0 = bm + wm + mt * 16 + g;
            if (r0 < M) {
                if (OUTHALF) {
                    __half2 hv = __floats2half2_rn(acc[mt][nt][0] + b0, acc[mt][nt][1] + b1);
                    *(__half2*)&Ch[(size_t)prow[mt][0] * 256 + col] = hv;
                } else {
                    *(float2*)&C[(size_t)r0 * N + col] =
                        make_float2(acc[mt][nt][0] + b0, acc[mt][nt][1] + b1);
                }
            }
            int r1 = r0 + 8;
            if (r1 < M) {
                if (OUTHALF) {
                    __half2 hv = __floats2half2_rn(acc[mt][nt][2] + b0, acc[mt][nt][3] + b1);
                    *(__half2*)&Ch[(size_t)prow[mt][1] * 256 + col] = hv;
                } else {
                    *(float2*)&C[(size_t)r1 * N + col] =
                        make_float2(acc[mt][nt][2] + b0, acc[mt][nt][3] + b1);
                }
            }
        }
    }
}

// ---------------------------------------------------------------------------
// Weight prep (single launch): Wv, merged Ws|Wa, Wo; merged bias.
// ---------------------------------------------------------------------------
__global__ void prep_weights(const float* __restrict__ Wv,
                             const float* __restrict__ Ws,
                             const float* __restrict__ Wa,
                             const float* __restrict__ Wo,
                             const float* __restrict__ bs,
                             const float* __restrict__ ba,
                             __nv_bfloat16* __restrict__ vh, __nv_bfloat16* __restrict__ vl,
                             __nv_bfloat16* __restrict__ qh, __nv_bfloat16* __restrict__ ql,
                             __nv_bfloat16* __restrict__ oh, __nv_bfloat16* __restrict__ ol,
                             float* __restrict__ bq)
{
    int idx = blockIdx.x * 256 + threadIdx.x;
    const float* W;
    __nv_bfloat16 *hi, *lo;
    int N, base, nofs;
    if (idx < 65536)        { W = Wv; hi = vh; lo = vl; N = 256; base = 0;      nofs = 0; }
    else if (idx < 131072)  { W = Ws; hi = qh; lo = ql; N = 256; base = 65536;  nofs = 0; }
    else if (idx < 163840)  { W = Wa; hi = qh; lo = ql; N = 128; base = 131072; nofs = 256; }
    else if (idx < 229376)  { W = Wo; hi = oh; lo = ol; N = 256; base = 163840; nofs = 0; }
    else if (idx < 229376 + 256) { bq[idx - 229376] = bs[idx - 229376]; return; }
    else if (idx < 229376 + 384) { bq[idx - 229376] = ba[idx - 229632]; return; }
    else return;
    int j = idx - base;
    int k = j / N, n = j % N + nofs;
    float v = W[j];
    __nv_bfloat16 h = __float2bfloat16(v);
    hi[n * 256 + k] = h;
    lo[n * 256 + k] = __float2bfloat16(v - __bfloat162float(h));
}

// ---------------------------------------------------------------------------
// Sampling kernel (unchanged from R6): padded value, no per-iter ALU.
// ---------------------------------------------------------------------------
__global__ __launch_bounds__(256) void msda_sample(
    const __half* __restrict__ value,    // PADDED [45822,256] fp16
    const float* __restrict__ qout,      // [Lq,384] offsets|logits
    const float* __restrict__ rp,        // [Lq,4,2]
    __nv_bfloat16* __restrict__ acch,
    __nv_bfloat16* __restrict__ accl)
{
    constexpr int WW[4] = {180, 90, 45, 23};
    constexpr int PB[4] = {0, 33856, 42692, 45093};

    const int q = blockIdx.x;
    const int h = threadIdx.x >> 5;
    const int lane = threadIdx.x & 31;
    const int cr = lane >> 3;
    const int e  = lane & 7;
    const int cx1 = cr & 1, cy1 = cr >> 1;

    float lg = -1e30f;
    if (lane < 16) lg = qout[q * 384 + 256 + h * 16 + lane];
    float m = lg;
#pragma unroll
    for (int s = 16; s > 0; s >>= 1)
        m = fmaxf(m, __shfl_xor_sync(0xffffffffu, m, s));
    float eo = (lane < 16) ? __expf(lg - m) : 0.f;
    float ssum = eo;
#pragma unroll
    for (int s = 16; s > 0; s >>= 1)
        ssum += __shfl_xor_sync(0xffffffffu, ssum, s);
    const float aw = eo / ssum;

    int   Gbase = 0;
    float Gadx = 0.f, Ga1x = 0.f, Gdy = 0.f;
    if (lane < 16) {
        const int l = lane >> 2;
        const int p = lane & 3;
        const int W = WW[l];
        const float rx = rp[(q * 4 + l) * 2 + 0];
        const float ry = rp[(q * 4 + l) * 2 + 1];
        const int oj = q * 384 + (((h * 4 + l) * 4) + p) * 2;
        const float x = fmaf(rx, (float)W, qout[oj + 0]) - 0.5f;
        const float y = fmaf(ry, (float)W, qout[oj + 1]) - 0.5f;
        const float xf = floorf(x), yf = floorf(y);
        const float dx = x - xf, dy = y - yf;
        const int xc = min(max((int)xf, -2), W);
        const int yc = min(max((int)yf, -2), W);
        Gbase = (PB[l] + (yc + 2) * (W + 4) + (xc + 2)) * 512;
        Gadx = aw * dx;
        Ga1x = aw - Gadx;
        Gdy  = dy;
    }
    int cstep[4];
#pragma unroll
    for (int l = 0; l < 4; l++)
        cstep[l] = (cy1 * (WW[l] + 4) + cx1) * 512;

    const char* __restrict__ vb = (const char*)value + h * 64 + e * 8;
    float4 acc = make_float4(0.f, 0.f, 0.f, 0.f);

#pragma unroll
    for (int i = 0; i < 16; i++) {
        const int l = i >> 2;
        const int   b   = __shfl_sync(0xffffffffu, Gbase, i);
        const float adx = __shfl_sync(0xffffffffu, Gadx, i);
        const float a1x = __shfl_sync(0xffffffffu, Ga1x, i);
        const float dyv = __shfl_sync(0xffffffffu, Gdy, i);
        const float wxa = cx1 ? adx : a1x;
        const float wy  = cy1 ? dyv : (1.f - dyv);
        const float w   = wxa * wy;

        const uint2 raw = *(const uint2*)(vb + (size_t)(uint32_t)(b + cstep[l]));
        const float2 f0 = __half22float2(*(const __half2*)&raw.x);
        const float2 f1 = __half22float2(*(const __half2*)&raw.y);
        acc.x = fmaf(w, f0.x, acc.x);
        acc.y = fmaf(w, f0.y, acc.y);
        acc.z = fmaf(w, f1.x, acc.z);
        acc.w = fmaf(w, f1.y, acc.w);
    }

#pragma unroll
    for (int s = 8; s <= 16; s <<= 1) {
        acc.x += __shfl_xor_sync(0xffffffffu, acc.x, s);
        acc.y += __shfl_xor_sync(0xffffffffu, acc.y, s);
        acc.z += __shfl_xor_sync(0xffffffffu, acc.z, s);
        acc.w += __shfl_xor_sync(0xffffffffu, acc.w, s);
    }
    if (lane < 8) {
        float vals[4] = {acc.x, acc.y, acc.z, acc.w};
        uint32_t hiw[2], low[2];
#pragma unroll
        for (int i = 0; i < 2; i++) {
            float a0 = vals[2 * i], a1 = vals[2 * i + 1];
            __nv_bfloat16 h0 = __float2bfloat16(a0);
            __nv_bfloat16 h1 = __float2bfloat16(a1);
            hiw[i] = packbf2(a0, a1);
            low[i] = packbf2(a0 - __bfloat162float(h0),
                             a1 - __bfloat162float(h1));
        }
        const size_t o = (size_t)q * 256 + h * 32 + lane * 4;
        *(uint2*)&acch[o] = make_uint2(hiw[0], hiw[1]);
        *(uint2*)&accl[o] = make_uint2(low[0], low[1]);
    }
}

// ---------------------------------------------------------------------------
// Launch
// ---------------------------------------------------------------------------
extern "C" void kernel_launch(void* const* d_in, const int* in_sizes, int n_in,
                              void* d_out, int out_size)
{
    const float* query    = (const float*)d_in[0];
    const float* value_in = (const float*)d_in[1];
    const float* rp       = (const float*)d_in[2];
    const float* Wv       = (const float*)d_in[3];
    const float* bv       = (const float*)d_in[4];
    const float* Ws       = (const float*)d_in[5];
    const float* bs       = (const float*)d_in[6];
    const float* Wa       = (const float*)d_in[7];
    const float* ba       = (const float*)d_in[8];
    const float* Wo       = (const float*)d_in[9];
    const float* bo       = (const float*)d_in[10];
    float* out = (float*)d_out;

    __half* pvh;
    float *pq, *pbq;
    __nv_bfloat16 *pah, *pal;
    cudaGetSymbolAddress((void**)&pvh, g_value_h);
    cudaGetSymbolAddress((void**)&pq,  g_qout);
    cudaGetSymbolAddress((void**)&pah, g_acch);
    cudaGetSymbolAddress((void**)&pal, g_accl);
    cudaGetSymbolAddress((void**)&pbq, g_bq);
    __nv_bfloat16 *wvh, *wvl, *wqh, *wql, *woh, *wol;
    cudaGetSymbolAddress((void**)&wvh, g_Wvh);
    cudaGetSymbolAddress((void**)&wvl, g_Wvl);
    cudaGetSymbolAddress((void**)&wqh, g_Wqh);
    cudaGetSymbolAddress((void**)&wql, g_Wql);
    cudaGetSymbolAddress((void**)&woh, g_Woh);
    cudaGetSymbolAddress((void**)&wol, g_Wol);

    const int SMEM = 98304;   // 96KB -> 2 CTAs/SM
    cudaFuncSetAttribute(gemm_mma<false, true>,  cudaFuncAttributeMaxDynamicSharedMemorySize, SMEM);
    cudaFuncSetAttribute(gemm_mma<false, false>, cudaFuncAttributeMaxDynamicSharedMemorySize, SMEM);
    cudaFuncSetAttribute(gemm_mma<true,  false>, cudaFuncAttributeMaxDynamicSharedMemorySize, SMEM);

    const int M = LQ;
    const int GBY = (M + 127) / 128;  // 337
    dim3 blk(256);

    // Zero padded borders + weight prep
    zero_pads<<<(PADROWS * 16 + 255) / 256, 256>>>(pvh);
    prep_weights<<<(229376 + 384 + 255) / 256, 256>>>(Wv, Ws, Wa, Wo, bs, ba,
                                                      wvh, wvl, wqh, wql, woh, wol, pbq);

    // value projection -> fp16 padded layout
    gemm_mma<false, true><<<dim3(2, GBY), blk, SMEM>>>(
        value_in, nullptr, nullptr, wvh, wvl, bv, nullptr, pvh, M, 256);
    // merged offsets+logits projection (N=384)
    gemm_mma<false, false><<<dim3(3, GBY), blk, SMEM>>>(
        query, nullptr, nullptr, wqh, wql, pbq, pq, nullptr, M, 384);

    // Deformable sampling (padded gather, pre-split bf16 out)
    msda_sample<<<M, 256>>>(pvh, pq, rp, pah, pal);

    // Output projection (A pre-split)
    gemm_mma<true, false><<<dim3(2, GBY), blk, SMEM>>>(
        nullptr, pah, pal, woh, wol, bo, out, nullptr, M, 256);
}

// round 8
// speedup vs baseline: 2.2254x; 1.1361x over previous
#include <cuda_runtime.h>
#include <cuda_bf16.h>
#include <cuda_fp16.h>
#include <cstdint>

// Problem constants
#define LQ      43054
#define NHEADS  8

// Padded value geometry: each level padded +2 on every side.
// L0 180x180 -> 184x184 (base 0),     L1 90x90 -> 94x94 (base 33856)
// L2 45x45   -> 49x49   (base 42692), L3 23x23 -> 27x27 (base 45093)
#define PADROWS 45822

// Scratch (device globals; no runtime allocation allowed)
__device__ __half g_value_h[PADROWS * 256];     // projected value, fp16, PADDED
__device__ float  g_qout[LQ * 384];             // [0,256)=offsets, [256,384)=logits
__device__ __half g_acch[LQ * 256];             // msda out hi (fp16)
__device__ __half g_accl[LQ * 256];             // msda out lo (fp16 residual)
// pre-transposed fp16 weights: [N, 256] K-major
__device__ __half g_Wv[256 * 256];
__device__ __half g_Wq[384 * 256];              // merged Ws|Wa
__device__ __half g_Wo[256 * 256];
__device__ float g_bq[384];                     // merged bias bs|ba

#define SW128(o) ((o) ^ (((o) >> 3) & 0x70))

__device__ __forceinline__ uint32_t smem_u32(const void* p) {
    uint32_t a;
    asm("{ .reg .u64 t; cvta.to.shared.u64 t, %1; cvt.u32.u64 %0, t; }" : "=r"(a) : "l"(p));
    return a;
}
__device__ __forceinline__ void ldsm4(uint32_t r[4], uint32_t addr) {
    asm volatile("ldmatrix.sync.aligned.m8n8.x4.shared.b16 {%0,%1,%2,%3}, [%4];"
        : "=r"(r[0]), "=r"(r[1]), "=r"(r[2]), "=r"(r[3]) : "r"(addr));
}
__device__ __forceinline__ void mma_f16(float d[4], const uint32_t a[4],
                                        uint32_t b0, uint32_t b1) {
    asm volatile("mma.sync.aligned.m16n8k16.row.col.f32.f16.f16.f32 "
        "{%0,%1,%2,%3}, {%4,%5,%6,%7}, {%8,%9}, {%0,%1,%2,%3};"
        : "+f"(d[0]), "+f"(d[1]), "+f"(d[2]), "+f"(d[3])
        : "r"(a[0]), "r"(a[1]), "r"(a[2]), "r"(a[3]), "r"(b0), "r"(b1));
}
__device__ __forceinline__ uint32_t packh2(float x, float y) {
    __half2 h = __floats2half2_rn(x, y);
    return *(uint32_t*)&h;
}
__device__ __forceinline__ void cpa16(uint32_t d, const void* s) {
    asm volatile("cp.async.cg.shared.global [%0], [%1], 16;" :: "r"(d), "l"(s));
}
#define CP_COMMIT() asm volatile("cp.async.commit_group;" ::: "memory")
template <int Ngrp>
__device__ __forceinline__ void cp_wait() {
    asm volatile("cp.async.wait_group %0;" :: "n"(Ngrp) : "memory");
}

// Map original value row -> padded row index (compile-time divisors).
__device__ __forceinline__ int pad_row(int r) {
    if (r < 32400) { int cy = r / 180, cx = r - cy * 180; return (cy + 2) * 184 + cx + 2; }
    if (r < 40500) { int rr = r - 32400; int cy = rr / 90, cx = rr - cy * 90; return 33856 + (cy + 2) * 94 + cx + 2; }
    if (r < 42525) { int rr = r - 40500; int cy = rr / 45, cx = rr - cy * 45; return 42692 + (cy + 2) * 49 + cx + 2; }
    { int rr = r - 42525; int cy = rr / 23, cx = rr - cy * 23; return 45093 + (cy + 2) * 27 + cx + 2; }
}

// ---------------------------------------------------------------------------
// Zero the padding borders of g_value_h each call.
// ---------------------------------------------------------------------------
__global__ __launch_bounds__(256) void zero_pads(__half* __restrict__ vp) {
    int idx = blockIdx.x * 256 + threadIdx.x;
    if (idx >= PADROWS * 16) return;
    int row = idx >> 4, c = idx & 15;
    bool pad;
    if (row < 33856)      { int py = row / 184, px = row - py * 184;
                            pad = (py < 2) | (py >= 182) | (px < 2) | (px >= 182); }
    else if (row < 42692) { int r2 = row - 33856; int py = r2 / 94, px = r2 - py * 94;
                            pad = (py < 2) | (py >= 92) | (px < 2) | (px >= 92); }
    else if (row < 45093) { int r2 = row - 42692; int py = r2 / 49, px = r2 - py * 49;
                            pad = (py < 2) | (py >= 47) | (px < 2) | (px >= 47); }
    else                  { int r2 = row - 45093; int py = r2 / 27, px = r2 - py * 27;
                            pad = (py < 2) | (py >= 25) | (px < 2) | (px >= 25); }
    if (pad) {
        uint4* d = (uint4*)((char*)vp + (size_t)row * 512 + c * 32);
        d[0] = make_uint4(0, 0, 0, 0);
        d[1] = make_uint4(0, 0, 0, 0);
    }
}

// ---------------------------------------------------------------------------
// Tensor-core GEMM, fp16 A-split-2 x fp16 B, 96KB smem -> 2 CTAs/SM.
//   C[M,N] = A[M,256] @ W[256,N] + bias   (2 MMA passes: AhB + AlB)
// A register-staged (fp32 split in-kernel, or pre-split fp16 hi/lo).
// B: all 4 K-chunks (16KB each) prefetched up-front via cp.async.
// CTA 128x128, 256 thr, 8 warps (4m x 2n), K chunks of 64.
// smem: A hi 0..16K, A lo 16..32K, B chunk c at 32K + c*16K.
// ---------------------------------------------------------------------------
template <bool ASPLIT, bool OUTHALF>
__global__ __launch_bounds__(256, 2) void gemm_mma(
    const float* __restrict__ A,
    const __half* __restrict__ AhG,
    const __half* __restrict__ AlG,
    const __half* __restrict__ B,
    const float* __restrict__ bias,
    float* __restrict__ C,
    __half* __restrict__ Ch,
    int M, int N)
{
    extern __shared__ char smem[];
    const uint32_t sb = smem_u32(smem);

    const int tid = threadIdx.x;
    const int wid = tid >> 5, lane = tid & 31;
    const int wm = (wid & 3) * 32;
    const int wn = (wid >> 2) * 64;
    const int bm = blockIdx.y * 128;
    const int bn = blockIdx.x * 128;

    float acc[2][8][4];
#pragma unroll
    for (int i = 0; i < 2; i++)
#pragma unroll
        for (int j = 0; j < 8; j++)
#pragma unroll
            for (int k = 0; k < 4; k++) acc[i][j][k] = 0.f;

    const int a_row = lane & 15;
    const int a_k8  = (lane >> 4) << 3;
    const int b_row = (lane & 7) + ((lane & 16) >> 1);
    const int b_k8  = lane & 8;

    const int ld_row = tid >> 1;          // 0..127
    const int ld_kh  = (tid & 1) * 32;    // 0 or 32 (k elements)
    const int grow   = bm + ld_row;
    const bool okA   = grow < M;

    // ---- async B chunk issue into chunk slot c (16KB each)
    auto issueB = [&](int c) {
        const int k0 = c * 64;
        const int n = bn + ld_row;
        const __half* s = &B[(size_t)n * 256 + k0 + ld_kh];
        const uint32_t bas = sb + 32768 + c * 16384;
#pragma unroll
        for (int jj = 0; jj < 4; jj++) {
            uint32_t off = SW128((uint32_t)(ld_row * 128 + (ld_kh + jj * 8) * 2));
            cpa16(bas + off, s + jj * 8);
        }
    };

    // ---- A register staging
    float4 vA[8];           // !ASPLIT
    uint4  sAh[4], sAl[4];  // ASPLIT
    auto stageA = [&](int c) {
        const int k0 = c * 64;
        if (!ASPLIT) {
            const float4* src = (const float4*)&A[(size_t)(okA ? grow : 0) * 256 + k0 + ld_kh];
#pragma unroll
            for (int j = 0; j < 8; j++)
                vA[j] = okA ? src[j] : make_float4(0.f, 0.f, 0.f, 0.f);
        } else {
            const uint4* sh = (const uint4*)&AhG[(size_t)(okA ? grow : 0) * 256 + k0 + ld_kh];
            const uint4* sl = (const uint4*)&AlG[(size_t)(okA ? grow : 0) * 256 + k0 + ld_kh];
#pragma unroll
            for (int j = 0; j < 4; j++) {
                sAh[j] = okA ? sh[j] : make_uint4(0, 0, 0, 0);
                sAl[j] = okA ? sl[j] : make_uint4(0, 0, 0, 0);
            }
        }
    };
    auto commitA = [&]() {
        if (!ASPLIT) {
#pragma unroll
            for (int jj = 0; jj < 4; jj++) {
                float4 v0 = vA[jj * 2 + 0];
                float4 v1 = vA[jj * 2 + 1];
                float vs[8] = {v0.x, v0.y, v0.z, v0.w, v1.x, v1.y, v1.z, v1.w};
                uint4 hi4, lo4;
                uint32_t* hp = (uint32_t*)&hi4;
                uint32_t* lp = (uint32_t*)&lo4;
#pragma unroll
                for (int i = 0; i < 4; i++) {
                    float a0 = vs[2 * i], a1 = vs[2 * i + 1];
                    float h0 = __half2float(__float2half_rn(a0));
                    float h1 = __half2float(__float2half_rn(a1));
                    hp[i] = packh2(a0, a1);
                    lp[i] = packh2(a0 - h0, a1 - h1);
                }
                uint32_t off = SW128((uint32_t)(ld_row * 128 + (ld_kh + jj * 8) * 2));
                *(uint4*)(smem + off) = hi4;
                *(uint4*)(smem + 16384 + off) = lo4;
            }
        } else {
#pragma unroll
            for (int jj = 0; jj < 4; jj++) {
                uint32_t off = SW128((uint32_t)(ld_row * 128 + (ld_kh + jj * 8) * 2));
                *(uint4*)(smem + off) = sAh[jj];
                *(uint4*)(smem + 16384 + off) = sAl[jj];
            }
        }
    };

    // ---- MMA over one 64-k chunk (2 passes: AhB + AlB)
    auto mma_chunk = [&](uint32_t bB) {
#pragma unroll
        for (int ks = 0; ks < 4; ks++) {
            uint32_t ah[2][4], al[2][4];
#pragma unroll
            for (int mt = 0; mt < 2; mt++) {
                uint32_t aoff = SW128((uint32_t)((wm + mt * 16 + a_row) * 128 +
                                                 (ks * 16 + a_k8) * 2));
                ldsm4(ah[mt], sb + aoff);
                ldsm4(al[mt], sb + 16384 + aoff);
            }
#pragma unroll
            for (int ng = 0; ng < 4; ng++) {
                uint32_t boff = SW128((uint32_t)((wn + ng * 16 + b_row) * 128 +
                                                 (ks * 16 + b_k8) * 2));
                uint32_t b4[4];
                ldsm4(b4, bB + boff);
#pragma unroll
                for (int mt = 0; mt < 2; mt++) {
                    mma_f16(acc[mt][ng * 2 + 0], ah[mt], b4[0], b4[1]);
                    mma_f16(acc[mt][ng * 2 + 0], al[mt], b4[0], b4[1]);
                    mma_f16(acc[mt][ng * 2 + 1], ah[mt], b4[2], b4[3]);
                    mma_f16(acc[mt][ng * 2 + 1], al[mt], b4[2], b4[3]);
                }
            }
        }
    };

    // schedule: all 4 B chunks up-front (4 groups); A staged one ahead.
    issueB(0); CP_COMMIT();
    issueB(1); CP_COMMIT();
    issueB(2); CP_COMMIT();
    issueB(3); CP_COMMIT();
    stageA(0);
#pragma unroll
    for (int c = 0; c < 4; c++) {
        if (c > 0) __syncthreads();          // mma(c-1) done before A overwrite
        commitA();
        if (c < 3) stageA(c + 1);
        if (c == 0) cp_wait<3>();
        else if (c == 1) cp_wait<2>();
        else if (c == 2) cp_wait<1>();
        else cp_wait<0>();
        __syncthreads();
        mma_chunk(sb + 32768 + c * 16384);
    }

    // ---- epilogue
    const int g = lane >> 2;
    const int cbase = bn + wn + (lane & 3) * 2;
    int prow[2][2];
    if (OUTHALF) {
#pragma unroll
        for (int mt = 0; mt < 2; mt++) {
            int r0 = bm + wm + mt * 16 + g;
            prow[mt][0] = (r0 < M) ? pad_row(r0) : 0;
            prow[mt][1] = (r0 + 8 < M) ? pad_row(r0 + 8) : 0;
        }
    }
#pragma unroll
    for (int nt = 0; nt < 8; nt++) {
        const int col = cbase + nt * 8;
        const float b0 = bias[col], b1 = bias[col + 1];
#pragma unroll
        for (int mt = 0; mt < 2; mt++) {
            int r0 = bm + wm + mt * 16 + g;
            if (r0 < M) {
                if (OUTHALF) {
                    __half2 hv = __floats2half2_rn(acc[mt][nt][0] + b0, acc[mt][nt][1] + b1);
                    *(__half2*)&Ch[(size_t)prow[mt][0] * 256 + col] = hv;
                } else {
                    *(float2*)&C[(size_t)r0 * N + col] =
                        make_float2(acc[mt][nt][0] + b0, acc[mt][nt][1] + b1);
                }
            }
            int r1 = r0 + 8;
            if (r1 < M) {
                if (OUTHALF) {
                    __half2 hv = __floats2half2_rn(acc[mt][nt][2] + b0, acc[mt][nt][3] + b1);
                    *(__half2*)&Ch[(size_t)prow[mt][1] * 256 + col] = hv;
                } else {
                    *(float2*)&C[(size_t)r1 * N + col] =
                        make_float2(acc[mt][nt][2] + b0, acc[mt][nt][3] + b1);
                }
            }
        }
    }
}

// ---------------------------------------------------------------------------
// Weight prep (single launch): fp16 transposed weights + merged bias.
// ---------------------------------------------------------------------------
__global__ void prep_weights(const float* __restrict__ Wv,
                             const float* __restrict__ Ws,
                             const float* __restrict__ Wa,
                             const float* __restrict__ Wo,
                             const float* __restrict__ bs,
                             const float* __restrict__ ba,
                             __half* __restrict__ wv,
                             __half* __restrict__ wq,
                             __half* __restrict__ wo,
                             float* __restrict__ bq)
{
    int idx = blockIdx.x * 256 + threadIdx.x;
    const float* W;
    __half* dst;
    int N, base, nofs;
    if (idx < 65536)        { W = Wv; dst = wv; N = 256; base = 0;      nofs = 0; }
    else if (idx < 131072)  { W = Ws; dst = wq; N = 256; base = 65536;  nofs = 0; }
    else if (idx < 163840)  { W = Wa; dst = wq; N = 128; base = 131072; nofs = 256; }
    else if (idx < 229376)  { W = Wo; dst = wo; N = 256; base = 163840; nofs = 0; }
    else if (idx < 229376 + 256) { bq[idx - 229376] = bs[idx - 229376]; return; }
    else if (idx < 229376 + 384) { bq[idx - 229376] = ba[idx - 229632]; return; }
    else return;
    int j = idx - base;
    int k = j / N, n = j % N + nofs;
    dst[n * 256 + k] = __float2half_rn(W[j]);
}

// ---------------------------------------------------------------------------
// Sampling kernel: padded value, no per-iter ALU; fp16 hi/lo split output.
// ---------------------------------------------------------------------------
__global__ __launch_bounds__(256) void msda_sample(
    const __half* __restrict__ value,    // PADDED [45822,256] fp16
    const float* __restrict__ qout,      // [Lq,384] offsets|logits
    const float* __restrict__ rp,        // [Lq,4,2]
    __half* __restrict__ acch,
    __half* __restrict__ accl)
{
    constexpr int WW[4] = {180, 90, 45, 23};
    constexpr int PB[4] = {0, 33856, 42692, 45093};

    const int q = blockIdx.x;
    const int h = threadIdx.x >> 5;
    const int lane = threadIdx.x & 31;
    const int cr = lane >> 3;
    const int e  = lane & 7;
    const int cx1 = cr & 1, cy1 = cr >> 1;

    float lg = -1e30f;
    if (lane < 16) lg = qout[q * 384 + 256 + h * 16 + lane];
    float m = lg;
#pragma unroll
    for (int s = 16; s > 0; s >>= 1)
        m = fmaxf(m, __shfl_xor_sync(0xffffffffu, m, s));
    float eo = (lane < 16) ? __expf(lg - m) : 0.f;
    float ssum = eo;
#pragma unroll
    for (int s = 16; s > 0; s >>= 1)
        ssum += __shfl_xor_sync(0xffffffffu, ssum, s);
    const float aw = eo / ssum;

    int   Gbase = 0;
    float Gadx = 0.f, Ga1x = 0.f, Gdy = 0.f;
    if (lane < 16) {
        const int l = lane >> 2;
        const int p = lane & 3;
        const int W = WW[l];
        const float rx = rp[(q * 4 + l) * 2 + 0];
        const float ry = rp[(q * 4 + l) * 2 + 1];
        const int oj = q * 384 + (((h * 4 + l) * 4) + p) * 2;
        const float x = fmaf(rx, (float)W, qout[oj + 0]) - 0.5f;
        const float y = fmaf(ry, (float)W, qout[oj + 1]) - 0.5f;
        const float xf = floorf(x), yf = floorf(y);
        const float dx = x - xf, dy = y - yf;
        const int xc = min(max((int)xf, -2), W);
        const int yc = min(max((int)yf, -2), W);
        Gbase = (PB[l] + (yc + 2) * (W + 4) + (xc + 2)) * 512;
        Gadx = aw * dx;
        Ga1x = aw - Gadx;
        Gdy  = dy;
    }
    int cstep[4];
#pragma unroll
    for (int l = 0; l < 4; l++)
        cstep[l] = (cy1 * (WW[l] + 4) + cx1) * 512;

    const char* __restrict__ vb = (const char*)value + h * 64 + e * 8;
    float4 acc = make_float4(0.f, 0.f, 0.f, 0.f);

#pragma unroll
    for (int i = 0; i < 16; i++) {
        const int l = i >> 2;
        const int   b   = __shfl_sync(0xffffffffu, Gbase, i);
        const float adx = __shfl_sync(0xffffffffu, Gadx, i);
        const float a1x = __shfl_sync(0xffffffffu, Ga1x, i);
        const float dyv = __shfl_sync(0xffffffffu, Gdy, i);
        const float wxa = cx1 ? adx : a1x;
        const float wy  = cy1 ? dyv : (1.f - dyv);
        const float w   = wxa * wy;

        const uint2 raw = *(const uint2*)(vb + (size_t)(uint32_t)(b + cstep[l]));
        const float2 f0 = __half22float2(*(const __half2*)&raw.x);
        const float2 f1 = __half22float2(*(const __half2*)&raw.y);
        acc.x = fmaf(w, f0.x, acc.x);
        acc.y = fmaf(w, f0.y, acc.y);
        acc.z = fmaf(w, f1.x, acc.z);
        acc.w = fmaf(w, f1.y, acc.w);
    }

#pragma unroll
    for (int s = 8; s <= 16; s <<= 1) {
        acc.x += __shfl_xor_sync(0xffffffffu, acc.x, s);
        acc.y += __shfl_xor_sync(0xffffffffu, acc.y, s);
        acc.z += __shfl_xor_sync(0xffffffffu, acc.z, s);
        acc.w += __shfl_xor_sync(0xffffffffu, acc.w, s);
    }
    if (lane < 8) {
        float vals[4] = {acc.x, acc.y, acc.z, acc.w};
        uint32_t hiw[2], low[2];
#pragma unroll
        for (int i = 0; i < 2; i++) {
            float a0 = vals[2 * i], a1 = vals[2 * i + 1];
            float h0 = __half2float(__float2half_rn(a0));
            float h1 = __half2float(__float2half_rn(a1));
            hiw[i] = packh2(a0, a1);
            low[i] = packh2(a0 - h0, a1 - h1);
        }
        const size_t o = (size_t)q * 256 + h * 32 + lane * 4;
        *(uint2*)&acch[o] = make_uint2(hiw[0], hiw[1]);
        *(uint2*)&accl[o] = make_uint2(low[0], low[1]);
    }
}

// ---------------------------------------------------------------------------
// Launch
// ---------------------------------------------------------------------------
extern "C" void kernel_launch(void* const* d_in, const int* in_sizes, int n_in,
                              void* d_out, int out_size)
{
    const float* query    = (const float*)d_in[0];
    const float* value_in = (const float*)d_in[1];
    const float* rp       = (const float*)d_in[2];
    const float* Wv       = (const float*)d_in[3];
    const float* bv       = (const float*)d_in[4];
    const float* Ws       = (const float*)d_in[5];
    const float* bs       = (const float*)d_in[6];
    const float* Wa       = (const float*)d_in[7];
    const float* ba       = (const float*)d_in[8];
    const float* Wo       = (const float*)d_in[9];
    const float* bo       = (const float*)d_in[10];
    float* out = (float*)d_out;

    __half *pvh, *pah, *pal, *pwv, *pwq, *pwo;
    float *pq, *pbq;
    cudaGetSymbolAddress((void**)&pvh, g_value_h);
    cudaGetSymbolAddress((void**)&pq,  g_qout);
    cudaGetSymbolAddress((void**)&pah, g_acch);
    cudaGetSymbolAddress((void**)&pal, g_accl);
    cudaGetSymbolAddress((void**)&pbq, g_bq);
    cudaGetSymbolAddress((void**)&pwv, g_Wv);
    cudaGetSymbolAddress((void**)&pwq, g_Wq);
    cudaGetSymbolAddress((void**)&pwo, g_Wo);

    const int SMEM = 98304;   // 32K A + 64K B (4 chunks) -> 2 CTAs/SM
    cudaFuncSetAttribute(gemm_mma<false, true>,  cudaFuncAttributeMaxDynamicSharedMemorySize, SMEM);
    cudaFuncSetAttribute(gemm_mma<false, false>, cudaFuncAttributeMaxDynamicSharedMemorySize, SMEM);
    cudaFuncSetAttribute(gemm_mma<true,  false>, cudaFuncAttributeMaxDynamicSharedMemorySize, SMEM);

    const int M = LQ;
    const int GBY = (M + 127) / 128;  // 337
    dim3 blk(256);

    // Zero padded borders + weight prep
    zero_pads<<<(PADROWS * 16 + 255) / 256, 256>>>(pvh);
    prep_weights<<<(229376 + 384 + 255) / 256, 256>>>(Wv, Ws, Wa, Wo, bs, ba,
                                                      pwv, pwq, pwo, pbq);

    // value projection -> fp16 padded layout
    gemm_mma<false, true><<<dim3(2, GBY), blk, SMEM>>>(
        value_in, nullptr, nullptr, pwv, bv, nullptr, pvh, M, 256);
    // merged offsets+logits projection (N=384)
    gemm_mma<false, false><<<dim3(3, GBY), blk, SMEM>>>(
        query, nullptr, nullptr, pwq, pbq, pq, nullptr, M, 384);

    // Deformable sampling (padded gather, fp16 split out)
    msda_sample<<<M, 256>>>(pvh, pq, rp, pah, pal);

    // Output projection (A pre-split fp16)
    gemm_mma<true, false><<<dim3(2, GBY), blk, SMEM>>>(
        nullptr, pah, pal, pwo, bo, out, nullptr, M, 256);
}

// round 9
// speedup vs baseline: 2.6133x; 1.1743x over previous
#include <cuda_runtime.h>
#include <cuda_bf16.h>
#include <cuda_fp16.h>
#include <cstdint>

// Problem constants
#define LQ      43054
#define NHEADS  8

// Padded value geometry: each level padded +2 on every side.
// L0 180x180 -> 184x184 (base 0),     L1 90x90 -> 94x94 (base 33856)
// L2 45x45   -> 49x49   (base 42692), L3 23x23 -> 27x27 (base 45093)
#define PADROWS 45822

// Scratch (device globals; no runtime allocation allowed)
__device__ __half g_value_h[PADROWS * 256];     // projected value, fp16, PADDED
__device__ float  g_qout[LQ * 384];             // [0,256)=offsets, [256,384)=logits
__device__ __half g_acch[LQ * 256];             // msda out hi (fp16)
__device__ __half g_accl[LQ * 256];             // msda out lo (fp16 residual)
// pre-transposed fp16 weights: [N, 256] K-major
__device__ __half g_Wv[256 * 256];
__device__ __half g_Wq[384 * 256];              // merged Ws|Wa
__device__ __half g_Wo[256 * 256];
__device__ float g_bq[384];                     // merged bias bs|ba

#define SW128(o) ((o) ^ (((o) >> 3) & 0x70))

__device__ __forceinline__ uint32_t smem_u32(const void* p) {
    uint32_t a;
    asm("{ .reg .u64 t; cvta.to.shared.u64 t, %1; cvt.u32.u64 %0, t; }" : "=r"(a) : "l"(p));
    return a;
}
__device__ __forceinline__ void ldsm4(uint32_t r[4], uint32_t addr) {
    asm volatile("ldmatrix.sync.aligned.m8n8.x4.shared.b16 {%0,%1,%2,%3}, [%4];"
        : "=r"(r[0]), "=r"(r[1]), "=r"(r[2]), "=r"(r[3]) : "r"(addr));
}
__device__ __forceinline__ void mma_f16(float d[4], const uint32_t a[4],
                                        uint32_t b0, uint32_t b1) {
    asm volatile("mma.sync.aligned.m16n8k16.row.col.f32.f16.f16.f32 "
        "{%0,%1,%2,%3}, {%4,%5,%6,%7}, {%8,%9}, {%0,%1,%2,%3};"
        : "+f"(d[0]), "+f"(d[1]), "+f"(d[2]), "+f"(d[3])
        : "r"(a[0]), "r"(a[1]), "r"(a[2]), "r"(a[3]), "r"(b0), "r"(b1));
}
__device__ __forceinline__ uint32_t packh2(float x, float y) {
    __half2 h = __floats2half2_rn(x, y);
    return *(uint32_t*)&h;
}
__device__ __forceinline__ void cpa16(uint32_t d, const void* s) {
    asm volatile("cp.async.cg.shared.global [%0], [%1], 16;" :: "r"(d), "l"(s));
}
#define CP_COMMIT() asm volatile("cp.async.commit_group;" ::: "memory")
template <int Ngrp>
__device__ __forceinline__ void cp_wait() {
    asm volatile("cp.async.wait_group %0;" :: "n"(Ngrp) : "memory");
}

// Map original value row -> padded row index (compile-time divisors).
__device__ __forceinline__ int pad_row(int r) {
    if (r < 32400) { int cy = r / 180, cx = r - cy * 180; return (cy + 2) * 184 + cx + 2; }
    if (r < 40500) { int rr = r - 32400; int cy = rr / 90, cx = rr - cy * 90; return 33856 + (cy + 2) * 94 + cx + 2; }
    if (r < 42525) { int rr = r - 40500; int cy = rr / 45, cx = rr - cy * 45; return 42692 + (cy + 2) * 49 + cx + 2; }
    { int rr = r - 42525; int cy = rr / 23, cx = rr - cy * 23; return 45093 + (cy + 2) * 27 + cx + 2; }
}

// ---------------------------------------------------------------------------
// Zero the padding borders of g_value_h each call.
// ---------------------------------------------------------------------------
__global__ __launch_bounds__(256) void zero_pads(__half* __restrict__ vp) {
    int idx = blockIdx.x * 256 + threadIdx.x;
    if (idx >= PADROWS * 16) return;
    int row = idx >> 4, c = idx & 15;
    bool pad;
    if (row < 33856)      { int py = row / 184, px = row - py * 184;
                            pad = (py < 2) | (py >= 182) | (px < 2) | (px >= 182); }
    else if (row < 42692) { int r2 = row - 33856; int py = r2 / 94, px = r2 - py * 94;
                            pad = (py < 2) | (py >= 92) | (px < 2) | (px >= 92); }
    else if (row < 45093) { int r2 = row - 42692; int py = r2 / 49, px = r2 - py * 49;
                            pad = (py < 2) | (py >= 47) | (px < 2) | (px >= 47); }
    else                  { int r2 = row - 45093; int py = r2 / 27, px = r2 - py * 27;
                            pad = (py < 2) | (py >= 25) | (px < 2) | (px >= 25); }
    if (pad) {
        uint4* d = (uint4*)((char*)vp + (size_t)row * 512 + c * 32);
        d[0] = make_uint4(0, 0, 0, 0);
        d[1] = make_uint4(0, 0, 0, 0);
    }
}

// ---------------------------------------------------------------------------
// Tensor-core GEMM, fp16, PASSES=1 (A fp16) or 2 (A split hi/lo).
//   C[M,N] = A[M,256] @ W[256,N] + bias
// A register-staged; B: all 4 K-chunks prefetched via cp.async.
// CTA 128x128, 256 thr, 8 warps (4m x 2n), K chunks of 64.
// smem: A hi 0..16K [, A lo 16..32K], B chunk c at PASSES*16K + c*16K.
// ---------------------------------------------------------------------------
template <bool ASPLIT, bool OUTHALF, int PASSES>
__global__ __launch_bounds__(256, 2) void gemm_mma(
    const float* __restrict__ A,
    const __half* __restrict__ AhG,
    const __half* __restrict__ AlG,
    const __half* __restrict__ B,
    const float* __restrict__ bias,
    float* __restrict__ C,
    __half* __restrict__ Ch,
    int M, int N)
{
    extern __shared__ char smem[];
    const uint32_t sb = smem_u32(smem);
    constexpr int BOFF = PASSES * 16384;

    const int tid = threadIdx.x;
    const int wid = tid >> 5, lane = tid & 31;
    const int wm = (wid & 3) * 32;
    const int wn = (wid >> 2) * 64;
    const int bm = blockIdx.y * 128;
    const int bn = blockIdx.x * 128;

    float acc[2][8][4];
#pragma unroll
    for (int i = 0; i < 2; i++)
#pragma unroll
        for (int j = 0; j < 8; j++)
#pragma unroll
            for (int k = 0; k < 4; k++) acc[i][j][k] = 0.f;

    const int a_row = lane & 15;
    const int a_k8  = (lane >> 4) << 3;
    const int b_row = (lane & 7) + ((lane & 16) >> 1);
    const int b_k8  = lane & 8;

    const int ld_row = tid >> 1;          // 0..127
    const int ld_kh  = (tid & 1) * 32;    // 0 or 32 (k elements)
    const int grow   = bm + ld_row;
    const bool okA   = grow < M;

    // ---- async B chunk issue into chunk slot c (16KB each)
    auto issueB = [&](int c) {
        const int k0 = c * 64;
        const int n = bn + ld_row;
        const __half* s = &B[(size_t)n * 256 + k0 + ld_kh];
        const uint32_t bas = sb + BOFF + c * 16384;
#pragma unroll
        for (int jj = 0; jj < 4; jj++) {
            uint32_t off = SW128((uint32_t)(ld_row * 128 + (ld_kh + jj * 8) * 2));
            cpa16(bas + off, s + jj * 8);
        }
    };

    // ---- A register staging
    float4 vA[8];           // !ASPLIT
    uint4  sAh[4], sAl[4];  // ASPLIT
    auto stageA = [&](int c) {
        const int k0 = c * 64;
        if (!ASPLIT) {
            const float4* src = (const float4*)&A[(size_t)(okA ? grow : 0) * 256 + k0 + ld_kh];
#pragma unroll
            for (int j = 0; j < 8; j++)
                vA[j] = okA ? src[j] : make_float4(0.f, 0.f, 0.f, 0.f);
        } else {
            const uint4* sh = (const uint4*)&AhG[(size_t)(okA ? grow : 0) * 256 + k0 + ld_kh];
            const uint4* sl = (const uint4*)&AlG[(size_t)(okA ? grow : 0) * 256 + k0 + ld_kh];
#pragma unroll
            for (int j = 0; j < 4; j++) {
                sAh[j] = okA ? sh[j] : make_uint4(0, 0, 0, 0);
                sAl[j] = okA ? sl[j] : make_uint4(0, 0, 0, 0);
            }
        }
    };
    auto commitA = [&]() {
        if (!ASPLIT) {
#pragma unroll
            for (int jj = 0; jj < 4; jj++) {
                float4 v0 = vA[jj * 2 + 0];
                float4 v1 = vA[jj * 2 + 1];
                float vs[8] = {v0.x, v0.y, v0.z, v0.w, v1.x, v1.y, v1.z, v1.w};
                uint4 hi4, lo4;
                uint32_t* hp = (uint32_t*)&hi4;
                uint32_t* lp = (uint32_t*)&lo4;
#pragma unroll
                for (int i = 0; i < 4; i++) {
                    float a0 = vs[2 * i], a1 = vs[2 * i + 1];
                    hp[i] = packh2(a0, a1);
                    if (PASSES == 2) {
                        float h0 = __half2float(__float2half_rn(a0));
                        float h1 = __half2float(__float2half_rn(a1));
                        lp[i] = packh2(a0 - h0, a1 - h1);
                    }
                }
                uint32_t off = SW128((uint32_t)(ld_row * 128 + (ld_kh + jj * 8) * 2));
                *(uint4*)(smem + off) = hi4;
                if (PASSES == 2) *(uint4*)(smem + 16384 + off) = lo4;
            }
        } else {
#pragma unroll
            for (int jj = 0; jj < 4; jj++) {
                uint32_t off = SW128((uint32_t)(ld_row * 128 + (ld_kh + jj * 8) * 2));
                *(uint4*)(smem + off) = sAh[jj];
                if (PASSES == 2) *(uint4*)(smem + 16384 + off) = sAl[jj];
            }
        }
    };

    // ---- MMA over one 64-k chunk
    auto mma_chunk = [&](uint32_t bB) {
#pragma unroll
        for (int ks = 0; ks < 4; ks++) {
            uint32_t ah[2][4], al[2][4];
#pragma unroll
            for (int mt = 0; mt < 2; mt++) {
                uint32_t aoff = SW128((uint32_t)((wm + mt * 16 + a_row) * 128 +
                                                 (ks * 16 + a_k8) * 2));
                ldsm4(ah[mt], sb + aoff);
                if (PASSES == 2) ldsm4(al[mt], sb + 16384 + aoff);
            }
#pragma unroll
            for (int ng = 0; ng < 4; ng++) {
                uint32_t boff = SW128((uint32_t)((wn + ng * 16 + b_row) * 128 +
                                                 (ks * 16 + b_k8) * 2));
                uint32_t b4[4];
                ldsm4(b4, bB + boff);
#pragma unroll
                for (int mt = 0; mt < 2; mt++) {
                    mma_f16(acc[mt][ng * 2 + 0], ah[mt], b4[0], b4[1]);
                    if (PASSES == 2) mma_f16(acc[mt][ng * 2 + 0], al[mt], b4[0], b4[1]);
                    mma_f16(acc[mt][ng * 2 + 1], ah[mt], b4[2], b4[3]);
                    if (PASSES == 2) mma_f16(acc[mt][ng * 2 + 1], al[mt], b4[2], b4[3]);
                }
            }
        }
    };

    // schedule: all 4 B chunks up-front (4 groups); A staged one ahead.
    issueB(0); CP_COMMIT();
    issueB(1); CP_COMMIT();
    issueB(2); CP_COMMIT();
    issueB(3); CP_COMMIT();
    stageA(0);
#pragma unroll
    for (int c = 0; c < 4; c++) {
        if (c > 0) __syncthreads();          // mma(c-1) done before A overwrite
        commitA();
        if (c < 3) stageA(c + 1);
        if (c == 0) cp_wait<3>();
        else if (c == 1) cp_wait<2>();
        else if (c == 2) cp_wait<1>();
        else cp_wait<0>();
        __syncthreads();
        mma_chunk(sb + BOFF + c * 16384);
    }

    // ---- epilogue
    const int g = lane >> 2;
    const int cbase = bn + wn + (lane & 3) * 2;
    int prow[2][2];
    if (OUTHALF) {
#pragma unroll
        for (int mt = 0; mt < 2; mt++) {
            int r0 = bm + wm + mt * 16 + g;
            prow[mt][0] = (r0 < M) ? pad_row(r0) : 0;
            prow[mt][1] = (r0 + 8 < M) ? pad_row(r0 + 8) : 0;
        }
    }
#pragma unroll
    for (int nt = 0; nt < 8; nt++) {
        const int col = cbase + nt * 8;
        const float b0 = bias[col], b1 = bias[col + 1];
#pragma unroll
        for (int mt = 0; mt < 2; mt++) {
            int r0 = bm + wm + mt * 16 + g;
            if (r0 < M) {
                if (OUTHALF) {
                    __half2 hv = __floats2half2_rn(acc[mt][nt][0] + b0, acc[mt][nt][1] + b1);
                    *(__half2*)&Ch[(size_t)prow[mt][0] * 256 + col] = hv;
                } else {
                    *(float2*)&C[(size_t)r0 * N + col] =
                        make_float2(acc[mt][nt][0] + b0, acc[mt][nt][1] + b1);
                }
            }
            int r1 = r0 + 8;
            if (r1 < M) {
                if (OUTHALF) {
                    __half2 hv = __floats2half2_rn(acc[mt][nt][2] + b0, acc[mt][nt][3] + b1);
                    *(__half2*)&Ch[(size_t)prow[mt][1] * 256 + col] = hv;
                } else {
                    *(float2*)&C[(size_t)r1 * N + col] =
                        make_float2(acc[mt][nt][2] + b0, acc[mt][nt][3] + b1);
                }
            }
        }
    }
}

// ---------------------------------------------------------------------------
// Weight prep (single launch): fp16 transposed weights + merged bias.
// ---------------------------------------------------------------------------
__global__ void prep_weights(const float* __restrict__ Wv,
                             const float* __restrict__ Ws,
                             const float* __restrict__ Wa,
                             const float* __restrict__ Wo,
                             const float* __restrict__ bs,
                             const float* __restrict__ ba,
                             __half* __restrict__ wv,
                             __half* __restrict__ wq,
                             __half* __restrict__ wo,
                             float* __restrict__ bq)
{
    int idx = blockIdx.x * 256 + threadIdx.x;
    const float* W;
    __half* dst;
    int N, base, nofs;
    if (idx < 65536)        { W = Wv; dst = wv; N = 256; base = 0;      nofs = 0; }
    else if (idx < 131072)  { W = Ws; dst = wq; N = 256; base = 65536;  nofs = 0; }
    else if (idx < 163840)  { W = Wa; dst = wq; N = 128; base = 131072; nofs = 256; }
    else if (idx < 229376)  { W = Wo; dst = wo; N = 256; base = 163840; nofs = 0; }
    else if (idx < 229376 + 256) { bq[idx - 229376] = bs[idx - 229376]; return; }
    else if (idx < 229376 + 384) { bq[idx - 229376] = ba[idx - 229632]; return; }
    else return;
    int j = idx - base;
    int k = j / N, n = j % N + nofs;
    dst[n * 256 + k] = __float2half_rn(W[j]);
}

// ---------------------------------------------------------------------------
// Sampling kernel v5: smem-staged (weight, byte-offset) pairs.
// Geometry lanes (0..15) compute all 4 corner (w, off) per point into smem;
// inner loop per lane: LDS.64 + LDG.64 + cvt + FFMA only.
// block=query, warp=head; lane: cr=lane>>3 corner, e=lane&7 channel-group.
// ---------------------------------------------------------------------------
__global__ __launch_bounds__(256) void msda_sample(
    const __half* __restrict__ value,    // PADDED [45822,256] fp16
    const float* __restrict__ qout,      // [Lq,384] offsets|logits
    const float* __restrict__ rp,        // [Lq,4,2]
    __half* __restrict__ acch,
    __half* __restrict__ accl)
{
    constexpr int WW[4] = {180, 90, 45, 23};
    constexpr int PB[4] = {0, 33856, 42692, 45093};

    __shared__ uint2 swo[NHEADS][16][4];   // [head][point][corner] = {w, off}

    const int q = blockIdx.x;
    const int h = threadIdx.x >> 5;
    const int lane = threadIdx.x & 31;
    const int cr = lane >> 3;
    const int e  = lane & 7;

    // softmax over this head's 16 logits
    float lg = -1e30f;
    if (lane < 16) lg = qout[q * 384 + 256 + h * 16 + lane];
    float m = lg;
#pragma unroll
    for (int s = 16; s > 0; s >>= 1)
        m = fmaxf(m, __shfl_xor_sync(0xffffffffu, m, s));
    float eo = (lane < 16) ? __expf(lg - m) : 0.f;
    float ssum = eo;
#pragma unroll
    for (int s = 16; s > 0; s >>= 1)
        ssum += __shfl_xor_sync(0xffffffffu, ssum, s);
    const float aw = eo / ssum;

    // geometry lanes: 4 corner (weight, byte-offset) pairs per (level,point)
    if (lane < 16) {
        const int l = lane >> 2;
        const int p = lane & 3;
        const int W = WW[l];
        const float rx = rp[(q * 4 + l) * 2 + 0];
        const float ry = rp[(q * 4 + l) * 2 + 1];
        const int oj = q * 384 + (((h * 4 + l) * 4) + p) * 2;
        const float x = fmaf(rx, (float)W, qout[oj + 0]) - 0.5f;
        const float y = fmaf(ry, (float)W, qout[oj + 1]) - 0.5f;
        const float xf = floorf(x), yf = floorf(y);
        const float dx = x - xf, dy = y - yf;
        const int xc = min(max((int)xf, -2), W);
        const int yc = min(max((int)yf, -2), W);
        const int B0 = (PB[l] + (yc + 2) * (W + 4) + (xc + 2)) * 512;
        const float wx1 = aw * dx;
        const float wx0 = aw - wx1;
#pragma unroll
        for (int c = 0; c < 4; c++) {
            const int cxx = c & 1, cyy = c >> 1;
            const int off = B0 + (cyy * (W + 4) + cxx) * 512;
            const float w = (cxx ? wx1 : wx0) * (cyy ? dy : (1.f - dy));
            swo[h][lane][c] = make_uint2(__float_as_uint(w), (uint32_t)off);
        }
    }
    __syncwarp();

    const char* __restrict__ vb = (const char*)value + h * 64 + e * 8;
    const uint2* __restrict__ sp = &swo[h][0][cr];
    float4 acc = make_float4(0.f, 0.f, 0.f, 0.f);

#pragma unroll
    for (int i = 0; i < 16; i++) {
        const uint2 wo = sp[i * 4];                  // LDS.64, imm offset
        const float w = __uint_as_float(wo.x);
        const uint2 raw = *(const uint2*)(vb + wo.y);
        const float2 f0 = __half22float2(*(const __half2*)&raw.x);
        const float2 f1 = __half22float2(*(const __half2*)&raw.y);
        acc.x = fmaf(w, f0.x, acc.x);
        acc.y = fmaf(w, f0.y, acc.y);
        acc.z = fmaf(w, f1.x, acc.z);
        acc.w = fmaf(w, f1.y, acc.w);
    }

    // reduce over 4 corner groups
#pragma unroll
    for (int s = 8; s <= 16; s <<= 1) {
        acc.x += __shfl_xor_sync(0xffffffffu, acc.x, s);
        acc.y += __shfl_xor_sync(0xffffffffu, acc.y, s);
        acc.z += __shfl_xor_sync(0xffffffffu, acc.z, s);
        acc.w += __shfl_xor_sync(0xffffffffu, acc.w, s);
    }
    if (lane < 8) {
        float vals[4] = {acc.x, acc.y, acc.z, acc.w};
        uint32_t hiw[2], low[2];
#pragma unroll
        for (int i = 0; i < 2; i++) {
            float a0 = vals[2 * i], a1 = vals[2 * i + 1];
            float h0 = __half2float(__float2half_rn(a0));
            float h1 = __half2float(__float2half_rn(a1));
            hiw[i] = packh2(a0, a1);
            low[i] = packh2(a0 - h0, a1 - h1);
        }
        const size_t o = (size_t)q * 256 + h * 32 + lane * 4;
        *(uint2*)&acch[o] = make_uint2(hiw[0], hiw[1]);
        *(uint2*)&accl[o] = make_uint2(low[0], low[1]);
    }
}

// ---------------------------------------------------------------------------
// Launch
// ---------------------------------------------------------------------------
extern "C" void kernel_launch(void* const* d_in, const int* in_sizes, int n_in,
                              void* d_out, int out_size)
{
    const float* query    = (const float*)d_in[0];
    const float* value_in = (const float*)d_in[1];
    const float* rp       = (const float*)d_in[2];
    const float* Wv       = (const float*)d_in[3];
    const float* bv       = (const float*)d_in[4];
    const float* Ws       = (const float*)d_in[5];
    const float* bs       = (const float*)d_in[6];
    const float* Wa       = (const float*)d_in[7];
    const float* ba       = (const float*)d_in[8];
    const float* Wo       = (const float*)d_in[9];
    const float* bo       = (const float*)d_in[10];
    float* out = (float*)d_out;

    __half *pvh, *pah, *pal, *pwv, *pwq, *pwo;
    float *pq, *pbq;
    cudaGetSymbolAddress((void**)&pvh, g_value_h);
    cudaGetSymbolAddress((void**)&pq,  g_qout);
    cudaGetSymbolAddress((void**)&pah, g_acch);
    cudaGetSymbolAddress((void**)&pal, g_accl);
    cudaGetSymbolAddress((void**)&pbq, g_bq);
    cudaGetSymbolAddress((void**)&pwv, g_Wv);
    cudaGetSymbolAddress((void**)&pwq, g_Wq);
    cudaGetSymbolAddress((void**)&pwo, g_Wo);

    const int SMEM2 = 98304;   // PASSES=2: 32K A + 64K B
    const int SMEM1 = 81920;   // PASSES=1: 16K A + 64K B
    cudaFuncSetAttribute(gemm_mma<false, true, 2>,  cudaFuncAttributeMaxDynamicSharedMemorySize, SMEM2);
    cudaFuncSetAttribute(gemm_mma<false, false, 1>, cudaFuncAttributeMaxDynamicSharedMemorySize, SMEM1);
    cudaFuncSetAttribute(gemm_mma<true,  false, 2>, cudaFuncAttributeMaxDynamicSharedMemorySize, SMEM2);

    const int M = LQ;
    const int GBY = (M + 127) / 128;  // 337
    dim3 blk(256);

    // Zero padded borders + weight prep
    zero_pads<<<(PADROWS * 16 + 255) / 256, 256>>>(pvh);
    prep_weights<<<(229376 + 384 + 255) / 256, 256>>>(Wv, Ws, Wa, Wo, bs, ba,
                                                      pwv, pwq, pwo, pbq);

    // value projection -> fp16 padded layout (split-2 for accuracy)
    gemm_mma<false, true, 2><<<dim3(2, GBY), blk, SMEM2>>>(
        value_in, nullptr, nullptr, pwv, bv, nullptr, pvh, M, 256);
    // merged offsets+logits projection (N=384), single-pass fp16
    gemm_mma<false, false, 1><<<dim3(3, GBY), blk, SMEM1>>>(
        query, nullptr, nullptr, pwq, pbq, pq, nullptr, M, 384);

    // Deformable sampling (padded gather, fp16 split out)
    msda_sample<<<M, 256>>>(pvh, pq, rp, pah, pal);

    // Output projection (A pre-split fp16, split-2)
    gemm_mma<true, false, 2><<<dim3(2, GBY), blk, SMEM2>>>(
        nullptr, pah, pal, pwo, bo, out, nullptr, M, 256);
}